// round 2
// baseline (speedup 1.0000x reference)
#include <cuda_runtime.h>
#include <cuda_bf16.h>
#include <math.h>

// Problem constants
#define NNODES   4096      // 64 samples * 64 agents
#define NAG      64        // agents per sample
#define NSAMP    64
#define FDIM     128
#define ZW       258       // 2*F + 2
#define LN2F     0.69314718055994530942f

// ---------------- scratch (device globals; no allocations allowed) ----------
__device__ float  g_A[NNODES * FDIM];   // exp(-Pf)
__device__ float  g_U[NNODES * FDIM];   // exp(-Qf)
__device__ float  g_B[NNODES * FDIM];   // exp(+Ps)
__device__ float  g_V[NNODES * FDIM];   // exp(+Qs)
__device__ float  g_agg[NNODES * FDIM];
__device__ float  g_x1[NNODES * FDIM];
__device__ double g_sum[2][FDIM];
__device__ double g_sq[2][FDIM];

// ---------------- zero stats -------------------------------------------------
__global__ void k_zero_stats() {
    int t = threadIdx.x;
    if (t < FDIM) {
        g_sum[0][t] = 0.0; g_sq[0][t] = 0.0;
        g_sum[1][t] = 0.0; g_sq[1][t] = 0.0;
    }
}

// ---------------- node GEMM + exp epilogue ----------------------------------
// Computes, for every node m and feature f:
//   Pf = sum_k x[m,k]*Wf[f,k]        + c0*Wf[f,256] + c1*Wf[f,257] + bf[f]
//   Qf = sum_k x[m,k]*Wf[f,128+k]    - c0*Wf[f,256] - c1*Wf[f,257]
//   Ps = sum_k x[m,k]*Ws[f,k]        + c0*Ws[f,256] + c1*Ws[f,257] + bs[f]
//   Qs = sum_k x[m,k]*Ws[f,128+k]    - c0*Ws[f,256] - c1*Ws[f,257]
// and stores A=exp(-Pf), U=exp(-Qf), B=exp(Ps), V=exp(Qs).
// Treated as C[4096,512] = X[4096,128] @ Wcat[512,128]^T, column c = g*128+f,
// g in {0:A, 1:U, 2:B, 3:V}.
__global__ __launch_bounds__(256) void k_gemm_abuv(
    const float* __restrict__ X,
    const float* __restrict__ C2,
    const float* __restrict__ Wf, const float* __restrict__ bf,
    const float* __restrict__ Ws, const float* __restrict__ bs)
{
    __shared__ float Xs[64][129];
    __shared__ float Wt[64][129];

    const int bm = blockIdx.x * 64;   // node tile base
    const int bn = blockIdx.y * 64;   // output-column tile base (0..511)
    const int tid = threadIdx.x;

    // Load X tile (coalesced)
    #pragma unroll
    for (int idx = tid; idx < 64 * 128; idx += 256) {
        int m = idx >> 7, k = idx & 127;
        Xs[m][k] = X[(bm + m) * FDIM + k];
    }
    // Load W tile (coalesced per row)
    #pragma unroll
    for (int idx = tid; idx < 64 * 128; idx += 256) {
        int cl = idx >> 7, k = idx & 127;
        int c = bn + cl;
        int g = c >> 7, f = c & 127;
        const float* wb = ((g < 2) ? Wf : Ws) + f * ZW + ((g & 1) ? 128 : 0);
        Wt[cl][k] = wb[k];
    }
    __syncthreads();

    const int tx = tid & 15;   // N direction (4 cols)
    const int ty = tid >> 4;   // M direction (4 rows)

    float acc[4][4];
    #pragma unroll
    for (int r = 0; r < 4; r++)
        #pragma unroll
        for (int c = 0; c < 4; c++) acc[r][c] = 0.f;

    #pragma unroll 8
    for (int k = 0; k < 128; k++) {
        float xs[4], ws[4];
        #pragma unroll
        for (int r = 0; r < 4; r++) xs[r] = Xs[ty * 4 + r][k];
        #pragma unroll
        for (int c = 0; c < 4; c++) ws[c] = Wt[tx * 4 + c][k];
        #pragma unroll
        for (int r = 0; r < 4; r++)
            #pragma unroll
            for (int c = 0; c < 4; c++)
                acc[r][c] = fmaf(xs[r], ws[c], acc[r][c]);
    }

    // Epilogue: centers term + bias + exp
    #pragma unroll
    for (int r = 0; r < 4; r++) {
        int m = bm + ty * 4 + r;
        float c0 = C2[m * 2 + 0];
        float c1 = C2[m * 2 + 1];
        #pragma unroll
        for (int cc = 0; cc < 4; cc++) {
            int c = bn + tx * 4 + cc;
            int g = c >> 7, f = c & 127;
            float v = acc[r][cc];
            if (g == 0) {
                float ce = fmaf(c0, Wf[f * ZW + 256], c1 * Wf[f * ZW + 257]);
                g_A[m * FDIM + f] = __expf(-(v + ce + bf[f]));
            } else if (g == 1) {
                float ce = fmaf(c0, Wf[f * ZW + 256], c1 * Wf[f * ZW + 257]);
                g_U[m * FDIM + f] = __expf(-(v - ce));
            } else if (g == 2) {
                float ce = fmaf(c0, Ws[f * ZW + 256], c1 * Ws[f * ZW + 257]);
                g_B[m * FDIM + f] = __expf(v + ce + bs[f]);
            } else {
                float ce = fmaf(c0, Ws[f * ZW + 256], c1 * Ws[f * ZW + 257]);
                g_V[m * FDIM + f] = __expf(v - ce);
            }
        }
    }
}

// ---------------- edge aggregation ------------------------------------------
// agg[i,f] = sum_{j != i, same sample} sigmoid(Pf_i+Qf_j) * softplus(Ps_i+Qs_j)
//          = sum_j  rcp(1 + A_i*U_j) * ln2 * log2(1 + B_i*V_j)   - self term.
// Block: one sample x 4 features. threads = 64 agents * 4 features.
// Also accumulates per-feature sum / sum-of-squares (BN stats) via atomics.
__global__ __launch_bounds__(256) void k_edge(int sidx)
{
    __shared__ float su[4][64];
    __shared__ float sv[4][64];
    __shared__ float wsum[8], wsq[8];

    const int tid  = threadIdx.x;
    const int i    = tid & 63;          // agent within sample
    const int fl   = tid >> 6;          // 0..3 local feature
    const int f    = blockIdx.y * 4 + fl;
    const int node = blockIdx.x * NAG + i;
    const int base = node * FDIM + f;

    const float a  = g_A[base];
    const float b  = g_B[base];
    const float u  = g_U[base];
    const float vv = g_V[base];
    su[fl][i] = u;
    sv[fl][i] = vv;
    __syncthreads();

    float acc0 = 0.f, acc1 = 0.f;
    #pragma unroll
    for (int j = 0; j < 64; j += 2) {
        float t1a = fmaf(a, su[fl][j],     1.f);
        float t2a = fmaf(b, sv[fl][j],     1.f);
        float t1b = fmaf(a, su[fl][j + 1], 1.f);
        float t2b = fmaf(b, sv[fl][j + 1], 1.f);
        float ra, rb;
        asm("rcp.approx.f32 %0, %1;" : "=f"(ra) : "f"(t1a));
        asm("rcp.approx.f32 %0, %1;" : "=f"(rb) : "f"(t1b));
        float la = __log2f(t2a);
        float lb = __log2f(t2b);
        acc0 = fmaf(ra, la, acc0);
        acc1 = fmaf(rb, lb, acc1);
    }
    // subtract self term (j == i)
    {
        float t1 = fmaf(a, u, 1.f);
        float t2 = fmaf(b, vv, 1.f);
        float r;
        asm("rcp.approx.f32 %0, %1;" : "=f"(r) : "f"(t1));
        float l = __log2f(t2);
        acc0 -= r * l;
    }
    const float aggv = (acc0 + acc1) * LN2F;
    g_agg[base] = aggv;

    // BN stats: reduce over the 64 agents of this block per feature
    float s = aggv, q = aggv * aggv;
    #pragma unroll
    for (int o = 16; o > 0; o >>= 1) {
        s += __shfl_down_sync(0xFFFFFFFFu, s, o);
        q += __shfl_down_sync(0xFFFFFFFFu, q, o);
    }
    if ((tid & 31) == 0) { wsum[tid >> 5] = s; wsq[tid >> 5] = q; }
    __syncthreads();
    if (tid < 4) {  // tid == fl; two warps per feature
        double S = (double)wsum[2 * tid] + (double)wsum[2 * tid + 1];
        double Q = (double)wsq[2 * tid]  + (double)wsq[2 * tid + 1];
        int ff = blockIdx.y * 4 + tid;
        atomicAdd(&g_sum[sidx][ff], S);
        atomicAdd(&g_sq[sidx][ff], Q);
    }
}

// ---------------- BatchNorm + residual + ReLU -------------------------------
__global__ __launch_bounds__(256) void k_bn(
    const float* __restrict__ xin,
    const float* __restrict__ gamma,
    const float* __restrict__ beta,
    float* __restrict__ out, int sidx)
{
    int idx = blockIdx.x * blockDim.x + threadIdx.x;   // 0 .. 4096*128-1
    int f = idx & 127;
    double mean = g_sum[sidx][f] * (1.0 / NNODES);
    double var  = g_sq[sidx][f] * (1.0 / NNODES) - mean * mean;
    float inv = (float)(1.0 / sqrt(var + 1e-5));
    float v = (g_agg[idx] - (float)mean) * inv * gamma[f] + beta[f] + xin[idx];
    out[idx] = fmaxf(v, 0.f);
}

// ---------------- launcher ---------------------------------------------------
extern "C" void kernel_launch(void* const* d_in, const int* in_sizes, int n_in,
                              void* d_out, int out_size)
{
    const float* gnn_in  = (const float*)d_in[0];
    const float* centers = (const float*)d_in[1];
    // d_in[2]=src, d_in[3]=dst are unused (graph structure is known statically)
    const float* Wf1 = (const float*)d_in[4];
    const float* bf1 = (const float*)d_in[5];
    const float* Ws1 = (const float*)d_in[6];
    const float* bs1 = (const float*)d_in[7];
    const float* g1  = (const float*)d_in[8];
    const float* be1 = (const float*)d_in[9];
    const float* Wf2 = (const float*)d_in[10];
    const float* bf2 = (const float*)d_in[11];
    const float* Ws2 = (const float*)d_in[12];
    const float* bs2 = (const float*)d_in[13];
    const float* g2  = (const float*)d_in[14];
    const float* be2 = (const float*)d_in[15];
    float* out = (float*)d_out;

    float* x1;
    cudaGetSymbolAddress((void**)&x1, g_x1);

    dim3 gemm_grid(NNODES / 64, 8);       // 64 x 8 blocks
    dim3 edge_grid(NSAMP, FDIM / 4);      // 64 x 32 blocks
    int bn_blocks = (NNODES * FDIM) / 256;

    k_zero_stats<<<1, 256>>>();

    // ---- layer 1 ----
    k_gemm_abuv<<<gemm_grid, 256>>>(gnn_in, centers, Wf1, bf1, Ws1, bs1);
    k_edge<<<edge_grid, 256>>>(0);
    k_bn<<<bn_blocks, 256>>>(gnn_in, g1, be1, x1, 0);

    // ---- layer 2 ----
    k_gemm_abuv<<<gemm_grid, 256>>>(x1, centers, Wf2, bf2, Ws2, bs2);
    k_edge<<<edge_grid, 256>>>(1);
    k_bn<<<bn_blocks, 256>>>(x1, g2, be2, out, 1);
}

// round 3
// speedup vs baseline: 1.9901x; 1.9901x over previous
#include <cuda_runtime.h>
#include <cuda_bf16.h>
#include <math.h>

// Problem constants
#define NNODES   4096      // 64 samples * 64 agents
#define NAG      64        // agents per sample
#define NSAMP    64
#define FDIM     128
#define ZW       258       // 2*F + 2
#define LN2F     0.69314718055994530942f

// ---------------- scratch (device globals; no allocations allowed) ----------
// g_E[0]=A=exp(-Pf), g_E[1]=U=exp(-Qf), g_E[2]=B=exp(+Ps), g_E[3]=V=exp(+Qs)
__device__ __align__(16) float  g_E[4][NNODES * FDIM];
__device__ __align__(16) float  g_agg[NNODES * FDIM];
__device__ __align__(16) float  g_x1[NNODES * FDIM];
__device__ double g_sum[2][FDIM];
__device__ double g_sq[2][FDIM];

// ---------------- zero stats -------------------------------------------------
__global__ void k_zero_stats() {
    int t = threadIdx.x;
    if (t < FDIM) {
        g_sum[0][t] = 0.0; g_sq[0][t] = 0.0;
        g_sum[1][t] = 0.0; g_sq[1][t] = 0.0;
    }
}

// ---------------- tf32 mma helpers ------------------------------------------
__device__ __forceinline__ unsigned f2tf32(float x) {
    unsigned u;
    asm("cvt.rna.tf32.f32 %0, %1;" : "=r"(u) : "f"(x));
    return u;
}
__device__ __forceinline__ void mma_tf32(float c[4], const unsigned a[4], const unsigned b[2]) {
    asm volatile("mma.sync.aligned.m16n8k8.row.col.f32.tf32.tf32.f32 "
        "{%0,%1,%2,%3}, {%4,%5,%6,%7}, {%8,%9}, {%0,%1,%2,%3};"
        : "+f"(c[0]), "+f"(c[1]), "+f"(c[2]), "+f"(c[3])
        : "r"(a[0]), "r"(a[1]), "r"(a[2]), "r"(a[3]), "r"(b[0]), "r"(b[1]));
}

// ---------------- node GEMM (tf32 tensor core) + exp epilogue ---------------
// C[4096,512] = X[4096,128] @ Wcat[512,128]^T, column n = g*128+f,
// g in {0:A, 1:U, 2:B, 3:V}.  Epilogue adds center/bias terms and exps.
// Block tile: 128m x 64n, 256 threads (8 warps: 4 along m x 2 along n),
// warp tile 32m x 32n = 2x4 m16n8k8 mma tiles, K=128 fully smem-resident.
#define XS_STRIDE 132
#define GEMM_SMEM_FLOATS (128*XS_STRIDE + 64*XS_STRIDE + 64*3 + 128*2)
#define GEMM_SMEM_BYTES  (GEMM_SMEM_FLOATS * 4)

__global__ __launch_bounds__(256) void k_gemm_tf32(
    const float* __restrict__ X,
    const float* __restrict__ C2,
    const float* __restrict__ Wf, const float* __restrict__ bf,
    const float* __restrict__ Ws, const float* __restrict__ bs)
{
    extern __shared__ float smem[];
    float* Xs  = smem;                          // [128][132] (tf32 bits)
    float* Wt  = Xs + 128 * XS_STRIDE;          // [64][132]  (tf32 bits)
    float* wA  = Wt + 64 * XS_STRIDE;           // [64] center coeff 0 (signed)
    float* wB  = wA + 64;                       // [64] center coeff 1 (signed)
    float* bb  = wB + 64;                       // [64] bias term
    float* cs0 = bb + 64;                       // [128] centers
    float* cs1 = cs0 + 128;

    unsigned* Xu = (unsigned*)Xs;
    unsigned* Wu = (unsigned*)Wt;

    const int tid = threadIdx.x;
    const int bm  = blockIdx.x * 128;
    const int bn  = blockIdx.y * 64;

    // ---- load X tile, convert to tf32 ----
    #pragma unroll
    for (int idx = tid; idx < 128 * 32; idx += 256) {
        int m = idx >> 5, kq = idx & 31;
        float4 v = ((const float4*)X)[(bm + m) * 32 + kq];
        unsigned* dst = Xu + m * XS_STRIDE + kq * 4;
        uint4 o;
        o.x = f2tf32(v.x); o.y = f2tf32(v.y); o.z = f2tf32(v.z); o.w = f2tf32(v.w);
        *(uint4*)dst = o;
    }
    // ---- load W tile (rows of Wcat), convert to tf32 ----
    #pragma unroll
    for (int idx = tid; idx < 64 * 64; idx += 256) {
        int cl = idx >> 6, kh = idx & 63;
        int n = bn + cl;
        int g = n >> 7, f = n & 127;
        const float* wb = ((g < 2) ? Wf : Ws) + f * ZW + ((g & 1) ? 128 : 0);
        float2 v = ((const float2*)wb)[kh];
        unsigned* dst = Wu + cl * XS_STRIDE + kh * 2;
        uint2 o; o.x = f2tf32(v.x); o.y = f2tf32(v.y);
        *(uint2*)dst = o;
    }
    // ---- small epilogue tables ----
    if (tid < 64) {
        int n = bn + tid;
        int g = n >> 7, f = n & 127;
        const float* wsel = (g < 2) ? Wf : Ws;
        float sgn = (g & 1) ? -1.f : 1.f;     // g odd: Q-side -> minus center term
        wA[tid] = sgn * wsel[f * ZW + 256];
        wB[tid] = sgn * wsel[f * ZW + 257];
        bb[tid] = (g == 0) ? bf[f] : ((g == 2) ? bs[f] : 0.f);
    }
    if (tid < 128) {
        cs0[tid] = C2[(bm + tid) * 2 + 0];
        cs1[tid] = C2[(bm + tid) * 2 + 1];
    }
    __syncthreads();

    const int wid   = tid >> 5;
    const int lane  = tid & 31;
    const int group = lane >> 2;
    const int tg    = lane & 3;
    const int wm    = (wid & 3) * 32;
    const int wn    = (wid >> 2) * 32;

    float acc[2][4][4];
    #pragma unroll
    for (int mt = 0; mt < 2; mt++)
        #pragma unroll
        for (int nt = 0; nt < 4; nt++)
            #pragma unroll
            for (int c = 0; c < 4; c++) acc[mt][nt][c] = 0.f;

    #pragma unroll
    for (int ks = 0; ks < 16; ks++) {
        const int kb = ks * 8;
        unsigned af[2][4], bfr[4][2];
        #pragma unroll
        for (int mt = 0; mt < 2; mt++) {
            int r = wm + mt * 16 + group;
            af[mt][0] = Xu[r * XS_STRIDE + kb + tg];
            af[mt][1] = Xu[(r + 8) * XS_STRIDE + kb + tg];
            af[mt][2] = Xu[r * XS_STRIDE + kb + tg + 4];
            af[mt][3] = Xu[(r + 8) * XS_STRIDE + kb + tg + 4];
        }
        #pragma unroll
        for (int nt = 0; nt < 4; nt++) {
            int nn = wn + nt * 8 + group;
            bfr[nt][0] = Wu[nn * XS_STRIDE + kb + tg];
            bfr[nt][1] = Wu[nn * XS_STRIDE + kb + tg + 4];
        }
        #pragma unroll
        for (int mt = 0; mt < 2; mt++)
            #pragma unroll
            for (int nt = 0; nt < 4; nt++)
                mma_tf32(acc[mt][nt], af[mt], bfr[nt]);
    }

    // ---- epilogue: center term + bias + exp, scatter to g_E ----
    #pragma unroll
    for (int mt = 0; mt < 2; mt++) {
        int r0 = wm + mt * 16 + group;     // local m for c0,c1
        int r1 = r0 + 8;                   // local m for c2,c3
        float a0 = cs0[r0], a1 = cs1[r0];
        float b0 = cs0[r1], b1 = cs1[r1];
        #pragma unroll
        for (int nt = 0; nt < 4; nt++) {
            int cl = wn + nt * 8 + 2 * tg;
            #pragma unroll
            for (int cc = 0; cc < 4; cc++) {
                int cll = cl + (cc & 1);
                int n = bn + cll;
                int g = n >> 7, f = n & 127;
                float mc0 = (cc < 2) ? a0 : b0;
                float mc1 = (cc < 2) ? a1 : b1;
                int rl = (cc < 2) ? r0 : r1;
                float t = acc[mt][nt][cc] + mc0 * wA[cll] + mc1 * wB[cll] + bb[cll];
                float v = __expf((g < 2) ? -t : t);
                g_E[g][(bm + rl) * FDIM + f] = v;
            }
        }
    }
}

// ---------------- edge aggregation ------------------------------------------
// agg[i,f] = sum_{j != i, same sample} sigmoid(Pf_i+Qf_j) * softplus(Ps_i+Qs_j)
//          = sum_j rcp(1 + A_i*U_j) * ln2 * log2(1 + B_i*V_j)  - self term.
__global__ __launch_bounds__(256) void k_edge(int sidx)
{
    __shared__ float su[4][64];
    __shared__ float sv[4][64];
    __shared__ float wsum[8], wsq[8];

    const int tid  = threadIdx.x;
    const int i    = tid & 63;          // agent within sample
    const int fl   = tid >> 6;          // 0..3 local feature
    const int f    = blockIdx.y * 4 + fl;
    const int node = blockIdx.x * NAG + i;
    const int base = node * FDIM + f;

    const float a  = g_E[0][base];
    const float u  = g_E[1][base];
    const float b  = g_E[2][base];
    const float vv = g_E[3][base];
    su[fl][i] = u;
    sv[fl][i] = vv;
    __syncthreads();

    float acc0 = 0.f, acc1 = 0.f;
    #pragma unroll
    for (int j = 0; j < 64; j += 2) {
        float t1a = fmaf(a, su[fl][j],     1.f);
        float t2a = fmaf(b, sv[fl][j],     1.f);
        float t1b = fmaf(a, su[fl][j + 1], 1.f);
        float t2b = fmaf(b, sv[fl][j + 1], 1.f);
        float ra, rb;
        asm("rcp.approx.f32 %0, %1;" : "=f"(ra) : "f"(t1a));
        asm("rcp.approx.f32 %0, %1;" : "=f"(rb) : "f"(t1b));
        float la = __log2f(t2a);
        float lb = __log2f(t2b);
        acc0 = fmaf(ra, la, acc0);
        acc1 = fmaf(rb, lb, acc1);
    }
    // subtract self term (j == i)
    {
        float t1 = fmaf(a, u, 1.f);
        float t2 = fmaf(b, vv, 1.f);
        float r;
        asm("rcp.approx.f32 %0, %1;" : "=f"(r) : "f"(t1));
        float l = __log2f(t2);
        acc0 -= r * l;
    }
    const float aggv = (acc0 + acc1) * LN2F;
    g_agg[base] = aggv;

    // BN stats partial sums
    float s = aggv, q = aggv * aggv;
    #pragma unroll
    for (int o = 16; o > 0; o >>= 1) {
        s += __shfl_down_sync(0xFFFFFFFFu, s, o);
        q += __shfl_down_sync(0xFFFFFFFFu, q, o);
    }
    if ((tid & 31) == 0) { wsum[tid >> 5] = s; wsq[tid >> 5] = q; }
    __syncthreads();
    if (tid < 4) {
        double S = (double)wsum[2 * tid] + (double)wsum[2 * tid + 1];
        double Q = (double)wsq[2 * tid]  + (double)wsq[2 * tid + 1];
        int ff = blockIdx.y * 4 + tid;
        atomicAdd(&g_sum[sidx][ff], S);
        atomicAdd(&g_sq[sidx][ff], Q);
    }
}

// ---------------- BatchNorm + residual + ReLU (fp32, float4) ----------------
// scale/shift computed once per block in smem (FP64 only for 128 threads).
__global__ __launch_bounds__(256) void k_bn(
    const float* __restrict__ xin,
    const float* __restrict__ gamma,
    const float* __restrict__ beta,
    float* __restrict__ out, int sidx)
{
    __shared__ float sc[FDIM], sh[FDIM];
    const int t = threadIdx.x;
    if (t < FDIM) {
        double mean = g_sum[sidx][t] * (1.0 / NNODES);
        double var  = g_sq[sidx][t] * (1.0 / NNODES) - mean * mean;
        float inv = (float)(1.0 / sqrt(var + 1e-5));
        float g = gamma[t];
        sc[t] = inv * g;
        sh[t] = beta[t] - (float)mean * inv * g;
    }
    __syncthreads();

    const int base = blockIdx.x * 1024 + t * 4;   // element index (multiple of 4)
    const int f = (t * 4) & 127;
    float4 ag = *(const float4*)(g_agg + base);
    float4 xi = *(const float4*)(xin + base);
    float4 o;
    o.x = fmaxf(fmaf(ag.x, sc[f + 0], sh[f + 0]) + xi.x, 0.f);
    o.y = fmaxf(fmaf(ag.y, sc[f + 1], sh[f + 1]) + xi.y, 0.f);
    o.z = fmaxf(fmaf(ag.z, sc[f + 2], sh[f + 2]) + xi.z, 0.f);
    o.w = fmaxf(fmaf(ag.w, sc[f + 3], sh[f + 3]) + xi.w, 0.f);
    *(float4*)(out + base) = o;
}

// ---------------- launcher ---------------------------------------------------
extern "C" void kernel_launch(void* const* d_in, const int* in_sizes, int n_in,
                              void* d_out, int out_size)
{
    const float* gnn_in  = (const float*)d_in[0];
    const float* centers = (const float*)d_in[1];
    // d_in[2]=src, d_in[3]=dst unused (graph structure is static)
    const float* Wf1 = (const float*)d_in[4];
    const float* bf1 = (const float*)d_in[5];
    const float* Ws1 = (const float*)d_in[6];
    const float* bs1 = (const float*)d_in[7];
    const float* g1  = (const float*)d_in[8];
    const float* be1 = (const float*)d_in[9];
    const float* Wf2 = (const float*)d_in[10];
    const float* bf2 = (const float*)d_in[11];
    const float* Ws2 = (const float*)d_in[12];
    const float* bs2 = (const float*)d_in[13];
    const float* g2  = (const float*)d_in[14];
    const float* be2 = (const float*)d_in[15];
    float* out = (float*)d_out;

    float* x1;
    cudaGetSymbolAddress((void**)&x1, g_x1);

    static int smem_set = 0;
    if (!smem_set) {
        cudaFuncSetAttribute(k_gemm_tf32,
                             cudaFuncAttributeMaxDynamicSharedMemorySize,
                             GEMM_SMEM_BYTES);
        smem_set = 1;
    }

    dim3 gemm_grid(NNODES / 128, 8);      // 32 x 8 blocks
    dim3 edge_grid(NSAMP, FDIM / 4);      // 64 x 32 blocks
    int bn_blocks = (NNODES * FDIM) / 1024;

    k_zero_stats<<<1, 256>>>();

    // ---- layer 1 ----
    k_gemm_tf32<<<gemm_grid, 256, GEMM_SMEM_BYTES>>>(gnn_in, centers, Wf1, bf1, Ws1, bs1);
    k_edge<<<edge_grid, 256>>>(0);
    k_bn<<<bn_blocks, 256>>>(gnn_in, g1, be1, x1, 0);

    // ---- layer 2 ----
    k_gemm_tf32<<<gemm_grid, 256, GEMM_SMEM_BYTES>>>(x1, centers, Wf2, bf2, Ws2, bs2);
    k_edge<<<edge_grid, 256>>>(1);
    k_bn<<<bn_blocks, 256>>>(x1, g2, be2, out, 1);
}

// round 4
// speedup vs baseline: 2.2642x; 1.1378x over previous
#include <cuda_runtime.h>
#include <cuda_bf16.h>
#include <math.h>

// Problem constants
#define NNODES   4096      // 64 samples * 64 agents
#define NAG      64        // agents per sample
#define NSAMP    64
#define FDIM     128
#define ZW       258       // 2*F + 2
#define LN2F     0.69314718055994530942f

// ---------------- scratch (device globals; no allocations allowed) ----------
// g_E[0]=A=exp(-Pf), g_E[1]=U=exp(-Qf), g_E[2]=B=exp(+Ps), g_E[3]=V=exp(+Qs)
__device__ __align__(16) float  g_E[4][NNODES * FDIM];
__device__ __align__(16) float  g_agg[NNODES * FDIM];
__device__ __align__(16) float  g_x1[NNODES * FDIM];
__device__ double g_sum[2][FDIM];
__device__ double g_sq[2][FDIM];
__device__ __align__(16) float g_sc[2][FDIM];
__device__ __align__(16) float g_sh[2][FDIM];
__device__ int    g_cnt[2];          // zero-initialized; last edge block resets

// ---------------- tf32 mma helpers ------------------------------------------
__device__ __forceinline__ unsigned f2tf32(float x) {
    unsigned u;
    asm("cvt.rna.tf32.f32 %0, %1;" : "=r"(u) : "f"(x));
    return u;
}
__device__ __forceinline__ void mma_tf32(float c[4], const unsigned a[4], const unsigned b[2]) {
    asm volatile("mma.sync.aligned.m16n8k8.row.col.f32.tf32.tf32.f32 "
        "{%0,%1,%2,%3}, {%4,%5,%6,%7}, {%8,%9}, {%0,%1,%2,%3};"
        : "+f"(c[0]), "+f"(c[1]), "+f"(c[2]), "+f"(c[3])
        : "r"(a[0]), "r"(a[1]), "r"(a[2]), "r"(a[3]), "r"(b[0]), "r"(b[1]));
}

// ---------------- node GEMM (tf32 tensor core) + exp epilogue ---------------
// C[4096,512] = X[4096,128] @ Wcat[512,128]^T, column n = g*128+f,
// g in {0:A, 1:U, 2:B, 3:V}.  Epilogue adds center/bias terms and exps.
// Block tile: 128m x 64n, 256 threads (8 warps: 4 along m x 2 along n),
// warp tile 32m x 32n = 2x4 m16n8k8 mma tiles, K=128 fully smem-resident.
// Block (0,0) additionally zeroes this layer's BN stats + counter.
#define XS_STRIDE 132
#define GEMM_SMEM_FLOATS (128*XS_STRIDE + 64*XS_STRIDE + 64*3 + 128*2)
#define GEMM_SMEM_BYTES  (GEMM_SMEM_FLOATS * 4)

__global__ __launch_bounds__(256) void k_gemm_tf32(
    const float* __restrict__ X,
    const float* __restrict__ C2,
    const float* __restrict__ Wf, const float* __restrict__ bf,
    const float* __restrict__ Ws, const float* __restrict__ bs,
    int sidx)
{
    extern __shared__ float smem[];
    float* Xs  = smem;                          // [128][132] (tf32 bits)
    float* Wt  = Xs + 128 * XS_STRIDE;          // [64][132]  (tf32 bits)
    float* wA  = Wt + 64 * XS_STRIDE;           // [64] center coeff 0 (signed)
    float* wB  = wA + 64;                       // [64] center coeff 1 (signed)
    float* bb  = wB + 64;                       // [64] bias term
    float* cs0 = bb + 64;                       // [128] centers
    float* cs1 = cs0 + 128;

    unsigned* Xu = (unsigned*)Xs;
    unsigned* Wu = (unsigned*)Wt;

    const int tid = threadIdx.x;
    const int bm  = blockIdx.x * 128;
    const int bn  = blockIdx.y * 64;

    // zero BN stats for this layer (runs concurrently with the tile loads;
    // edge kernel only starts after this kernel fully retires)
    if (blockIdx.x == 0 && blockIdx.y == 0) {
        if (tid < FDIM) { g_sum[sidx][tid] = 0.0; g_sq[sidx][tid] = 0.0; }
        if (tid == 128) g_cnt[sidx] = 0;
    }

    // ---- load X tile, convert to tf32 ----
    #pragma unroll
    for (int idx = tid; idx < 128 * 32; idx += 256) {
        int m = idx >> 5, kq = idx & 31;
        float4 v = ((const float4*)X)[(bm + m) * 32 + kq];
        unsigned* dst = Xu + m * XS_STRIDE + kq * 4;
        uint4 o;
        o.x = f2tf32(v.x); o.y = f2tf32(v.y); o.z = f2tf32(v.z); o.w = f2tf32(v.w);
        *(uint4*)dst = o;
    }
    // ---- load W tile (rows of Wcat), convert to tf32 ----
    #pragma unroll
    for (int idx = tid; idx < 64 * 64; idx += 256) {
        int cl = idx >> 6, kh = idx & 63;
        int n = bn + cl;
        int g = n >> 7, f = n & 127;
        const float* wb = ((g < 2) ? Wf : Ws) + f * ZW + ((g & 1) ? 128 : 0);
        float2 v = ((const float2*)wb)[kh];
        unsigned* dst = Wu + cl * XS_STRIDE + kh * 2;
        uint2 o; o.x = f2tf32(v.x); o.y = f2tf32(v.y);
        *(uint2*)dst = o;
    }
    // ---- small epilogue tables ----
    if (tid < 64) {
        int n = bn + tid;
        int g = n >> 7, f = n & 127;
        const float* wsel = (g < 2) ? Wf : Ws;
        float sgn = (g & 1) ? -1.f : 1.f;     // g odd: Q-side -> minus center term
        wA[tid] = sgn * wsel[f * ZW + 256];
        wB[tid] = sgn * wsel[f * ZW + 257];
        bb[tid] = (g == 0) ? bf[f] : ((g == 2) ? bs[f] : 0.f);
    }
    if (tid < 128) {
        cs0[tid] = C2[(bm + tid) * 2 + 0];
        cs1[tid] = C2[(bm + tid) * 2 + 1];
    }
    __syncthreads();

    const int wid   = tid >> 5;
    const int lane  = tid & 31;
    const int group = lane >> 2;
    const int tg    = lane & 3;
    const int wm    = (wid & 3) * 32;
    const int wn    = (wid >> 2) * 32;

    float acc[2][4][4];
    #pragma unroll
    for (int mt = 0; mt < 2; mt++)
        #pragma unroll
        for (int nt = 0; nt < 4; nt++)
            #pragma unroll
            for (int c = 0; c < 4; c++) acc[mt][nt][c] = 0.f;

    #pragma unroll
    for (int ks = 0; ks < 16; ks++) {
        const int kb = ks * 8;
        unsigned af[2][4], bfr[4][2];
        #pragma unroll
        for (int mt = 0; mt < 2; mt++) {
            int r = wm + mt * 16 + group;
            af[mt][0] = Xu[r * XS_STRIDE + kb + tg];
            af[mt][1] = Xu[(r + 8) * XS_STRIDE + kb + tg];
            af[mt][2] = Xu[r * XS_STRIDE + kb + tg + 4];
            af[mt][3] = Xu[(r + 8) * XS_STRIDE + kb + tg + 4];
        }
        #pragma unroll
        for (int nt = 0; nt < 4; nt++) {
            int nn = wn + nt * 8 + group;
            bfr[nt][0] = Wu[nn * XS_STRIDE + kb + tg];
            bfr[nt][1] = Wu[nn * XS_STRIDE + kb + tg + 4];
        }
        #pragma unroll
        for (int mt = 0; mt < 2; mt++)
            #pragma unroll
            for (int nt = 0; nt < 4; nt++)
                mma_tf32(acc[mt][nt], af[mt], bfr[nt]);
    }

    // ---- epilogue: center term + bias + exp, scatter to g_E ----
    #pragma unroll
    for (int mt = 0; mt < 2; mt++) {
        int r0 = wm + mt * 16 + group;     // local m for c0,c1
        int r1 = r0 + 8;                   // local m for c2,c3
        float a0 = cs0[r0], a1 = cs1[r0];
        float b0 = cs0[r1], b1 = cs1[r1];
        #pragma unroll
        for (int nt = 0; nt < 4; nt++) {
            int cl = wn + nt * 8 + 2 * tg;
            #pragma unroll
            for (int cc = 0; cc < 4; cc++) {
                int cll = cl + (cc & 1);
                int n = bn + cll;
                int g = n >> 7, f = n & 127;
                float mc0 = (cc < 2) ? a0 : b0;
                float mc1 = (cc < 2) ? a1 : b1;
                int rl = (cc < 2) ? r0 : r1;
                float t = acc[mt][nt][cc] + mc0 * wA[cll] + mc1 * wB[cll] + bb[cll];
                float v = __expf((g < 2) ? -t : t);
                g_E[g][(bm + rl) * FDIM + f] = v;
            }
        }
    }
}

// ---------------- edge aggregation ------------------------------------------
// agg[i,f] = sum_{j != i, same sample} sigmoid(Pf_i+Qf_j) * softplus(Ps_i+Qs_j)
//          = sum_j rcp(1 + A_i*U_j) * ln2 * log2(1 + B_i*V_j)  - self term.
// 4-way reciprocal batching: one RCP per 4 j's via product of denominators.
// Last arriving block finalizes BN scale/shift (FP64 once, 128 threads).
__global__ __launch_bounds__(256) void k_edge(int sidx,
    const float* __restrict__ gamma, const float* __restrict__ beta)
{
    __shared__ float su[4][64];
    __shared__ float sv[4][64];
    __shared__ float wsum[8], wsq[8];
    __shared__ int   lastflag;

    const int tid  = threadIdx.x;
    const int i    = tid & 63;          // agent within sample
    const int fl   = tid >> 6;          // 0..3 local feature
    const int f    = blockIdx.y * 4 + fl;
    const int node = blockIdx.x * NAG + i;
    const int base = node * FDIM + f;

    const float a  = g_E[0][base];
    const float u  = g_E[1][base];
    const float b  = g_E[2][base];
    const float vv = g_E[3][base];
    su[fl][i] = u;
    sv[fl][i] = vv;
    __syncthreads();

    const float4* pu = (const float4*)su[fl];
    const float4* pv = (const float4*)sv[fl];

    float acc = 0.f;
    #pragma unroll
    for (int jq = 0; jq < 16; jq++) {
        float4 U4 = pu[jq];
        float4 V4 = pv[jq];
        float t10 = fmaf(a, U4.x, 1.f);
        float t11 = fmaf(a, U4.y, 1.f);
        float t12 = fmaf(a, U4.z, 1.f);
        float t13 = fmaf(a, U4.w, 1.f);
        float p01 = t10 * t11;
        float p23 = t12 * t13;
        float D   = p01 * p23;
        float r;
        asm("rcp.approx.f32 %0, %1;" : "=f"(r) : "f"(D));
        float l0 = __log2f(fmaf(b, V4.x, 1.f));
        float l1 = __log2f(fmaf(b, V4.y, 1.f));
        float l2 = __log2f(fmaf(b, V4.z, 1.f));
        float l3 = __log2f(fmaf(b, V4.w, 1.f));
        float n0 = t11 * p23;
        float n1 = t10 * p23;
        float n2 = p01 * t13;
        float n3 = p01 * t12;
        float s = fmaf(n0, l0, n1 * l1) + fmaf(n2, l2, n3 * l3);
        acc = fmaf(s, r, acc);
    }
    // subtract self term (j == i)
    {
        float t1 = fmaf(a, u, 1.f);
        float t2 = fmaf(b, vv, 1.f);
        float r;
        asm("rcp.approx.f32 %0, %1;" : "=f"(r) : "f"(t1));
        acc -= r * __log2f(t2);
    }
    const float aggv = acc * LN2F;
    g_agg[base] = aggv;

    // BN stats partial sums (per feature over this block's 64 agents)
    float s = aggv, q = aggv * aggv;
    #pragma unroll
    for (int o = 16; o > 0; o >>= 1) {
        s += __shfl_down_sync(0xFFFFFFFFu, s, o);
        q += __shfl_down_sync(0xFFFFFFFFu, q, o);
    }
    if ((tid & 31) == 0) { wsum[tid >> 5] = s; wsq[tid >> 5] = q; }
    __syncthreads();
    if (tid < 4) {
        double S = (double)wsum[2 * tid] + (double)wsum[2 * tid + 1];
        double Q = (double)wsq[2 * tid]  + (double)wsq[2 * tid + 1];
        int ff = blockIdx.y * 4 + tid;
        atomicAdd(&g_sum[sidx][ff], S);
        atomicAdd(&g_sq[sidx][ff], Q);
        __threadfence();
    }
    __syncthreads();

    // last-arriving block computes BN scale/shift once
    if (tid == 0) {
        int prev = atomicAdd(&g_cnt[sidx], 1);
        lastflag = (prev == NSAMP * (FDIM / 4) - 1);
    }
    __syncthreads();
    if (lastflag) {
        if (tid < FDIM) {
            double S = __ldcg(&g_sum[sidx][tid]);
            double Q = __ldcg(&g_sq[sidx][tid]);
            double mean = S * (1.0 / NNODES);
            double var  = Q * (1.0 / NNODES) - mean * mean;
            float inv = (float)(1.0 / sqrt(var + 1e-5));
            float g = gamma[tid];
            g_sc[sidx][tid] = inv * g;
            g_sh[sidx][tid] = beta[tid] - (float)mean * inv * g;
        }
    }
}

// ---------------- BatchNorm + residual + ReLU (pure fp32 stream) ------------
// 256 blocks x 256 threads x 2 float4 each. No smem, no syncthreads, no FP64.
__global__ __launch_bounds__(256) void k_bn(
    const float* __restrict__ xin,
    float* __restrict__ out, int sidx)
{
    const int t = threadIdx.x;
    const float* sc = g_sc[sidx];
    const float* sh = g_sh[sidx];

    #pragma unroll
    for (int rep = 0; rep < 2; rep++) {
        int q4 = blockIdx.x * 512 + rep * 256 + t;   // float4 index
        int base = q4 * 4;
        int f = base & 127;
        float4 ag = *(const float4*)(g_agg + base);
        float4 xi = *(const float4*)(xin + base);
        float4 scv = *(const float4*)(sc + f);
        float4 shv = *(const float4*)(sh + f);
        float4 o;
        o.x = fmaxf(fmaf(ag.x, scv.x, shv.x) + xi.x, 0.f);
        o.y = fmaxf(fmaf(ag.y, scv.y, shv.y) + xi.y, 0.f);
        o.z = fmaxf(fmaf(ag.z, scv.z, shv.z) + xi.z, 0.f);
        o.w = fmaxf(fmaf(ag.w, scv.w, shv.w) + xi.w, 0.f);
        *(float4*)(out + base) = o;
    }
}

// ---------------- launcher ---------------------------------------------------
extern "C" void kernel_launch(void* const* d_in, const int* in_sizes, int n_in,
                              void* d_out, int out_size)
{
    const float* gnn_in  = (const float*)d_in[0];
    const float* centers = (const float*)d_in[1];
    // d_in[2]=src, d_in[3]=dst unused (graph structure is static)
    const float* Wf1 = (const float*)d_in[4];
    const float* bf1 = (const float*)d_in[5];
    const float* Ws1 = (const float*)d_in[6];
    const float* bs1 = (const float*)d_in[7];
    const float* g1  = (const float*)d_in[8];
    const float* be1 = (const float*)d_in[9];
    const float* Wf2 = (const float*)d_in[10];
    const float* bf2 = (const float*)d_in[11];
    const float* Ws2 = (const float*)d_in[12];
    const float* bs2 = (const float*)d_in[13];
    const float* g2  = (const float*)d_in[14];
    const float* be2 = (const float*)d_in[15];
    float* out = (float*)d_out;

    float* x1;
    cudaGetSymbolAddress((void**)&x1, g_x1);

    static int smem_set = 0;
    if (!smem_set) {
        cudaFuncSetAttribute(k_gemm_tf32,
                             cudaFuncAttributeMaxDynamicSharedMemorySize,
                             GEMM_SMEM_BYTES);
        smem_set = 1;
    }

    dim3 gemm_grid(NNODES / 128, 8);      // 32 x 8 blocks
    dim3 edge_grid(NSAMP, FDIM / 4);      // 64 x 32 blocks
    int bn_blocks = (NNODES * FDIM) / (4 * 512);   // 256 blocks

    // ---- layer 1 ----
    k_gemm_tf32<<<gemm_grid, 256, GEMM_SMEM_BYTES>>>(gnn_in, centers, Wf1, bf1, Ws1, bs1, 0);
    k_edge<<<edge_grid, 256>>>(0, g1, be1);
    k_bn<<<bn_blocks, 256>>>(gnn_in, x1, 0);

    // ---- layer 2 ----
    k_gemm_tf32<<<gemm_grid, 256, GEMM_SMEM_BYTES>>>(x1, centers, Wf2, bf2, Ws2, bs2, 1);
    k_edge<<<edge_grid, 256>>>(1, g2, be2);
    k_bn<<<bn_blocks, 256>>>(x1, out, 1);
}

// round 5
// speedup vs baseline: 2.3243x; 1.0265x over previous
#include <cuda_runtime.h>
#include <cuda_bf16.h>
#include <math.h>

// Problem constants
#define NNODES   4096      // 64 samples * 64 agents
#define NAG      64        // agents per sample
#define NSAMP    64
#define FDIM     128
#define ZW       258       // 2*F + 2
#define LN2F     0.69314718055994530942f

// ---------------- scratch (device globals; no allocations allowed) ----------
// g_E[0]=A=exp(-Pf), g_E[1]=U=exp(-Qf), g_E[2]=B=exp(+Ps), g_E[3]=V=exp(+Qs)
__device__ __align__(16) float  g_E[4][NNODES * FDIM];
__device__ __align__(16) float  g_agg[NNODES * FDIM];
__device__ __align__(16) float  g_x1[NNODES * FDIM];
__device__ double g_sum[2][FDIM];
__device__ double g_sq[2][FDIM];
__device__ __align__(16) float g_sc[2][FDIM];
__device__ __align__(16) float g_sh[2][FDIM];
__device__ int    g_cnt[2];          // zero-initialized; last edge block resets

// ---------------- tf32 mma helpers ------------------------------------------
__device__ __forceinline__ unsigned f2tf32(float x) {
    unsigned u;
    asm("cvt.rna.tf32.f32 %0, %1;" : "=r"(u) : "f"(x));
    return u;
}
__device__ __forceinline__ void mma_tf32(float c[4], const unsigned a[4], const unsigned b[2]) {
    asm volatile("mma.sync.aligned.m16n8k8.row.col.f32.tf32.tf32.f32 "
        "{%0,%1,%2,%3}, {%4,%5,%6,%7}, {%8,%9}, {%0,%1,%2,%3};"
        : "+f"(c[0]), "+f"(c[1]), "+f"(c[2]), "+f"(c[3])
        : "r"(a[0]), "r"(a[1]), "r"(a[2]), "r"(a[3]), "r"(b[0]), "r"(b[1]));
}
__device__ __forceinline__ void ldsm_x4(unsigned r[4], unsigned saddr) {
    asm volatile("ldmatrix.sync.aligned.m8n8.x4.shared.b16 {%0,%1,%2,%3}, [%4];"
        : "=r"(r[0]), "=r"(r[1]), "=r"(r[2]), "=r"(r[3]) : "r"(saddr));
}
__device__ __forceinline__ void ldsm_x2(unsigned r[2], unsigned saddr) {
    asm volatile("ldmatrix.sync.aligned.m8n8.x2.shared.b16 {%0,%1}, [%2];"
        : "=r"(r[0]), "=r"(r[1]) : "r"(saddr));
}
__device__ __forceinline__ unsigned smem_u32(const void* p) {
    unsigned a;
    asm("{ .reg .u64 t; cvta.to.shared.u64 t, %1; cvt.u32.u64 %0, t; }"
        : "=r"(a) : "l"(p));
    return a;
}

// ---------------- node GEMM (tf32 tensor core) + exp epilogue ---------------
// C[4096,512] = X[4096,128] @ Wcat[512,128]^T, column n = g*128+f,
// g in {0:A, 1:U, 2:B, 3:V}.  Epilogue adds center/bias terms and exps.
// Block tile: 128m x 64n, 256 threads (8 warps: 4 along m x 2 along n),
// warp tile 32m x 32n = 2x4 m16n8k8 mma tiles, K=128 smem-resident.
// Fragments loaded via ldmatrix (LDSM.x4 for A, LDSM.x2 for B), 2-deep
// register pipeline over k-steps. Block (0,0) zeroes this layer's BN stats.
#define XS_STRIDE 132
#define GEMM_SMEM_FLOATS (128*XS_STRIDE + 64*XS_STRIDE + 64*3 + 128*2)
#define GEMM_SMEM_BYTES  (GEMM_SMEM_FLOATS * 4)

__global__ __launch_bounds__(256, 2) void k_gemm_tf32(
    const float* __restrict__ X,
    const float* __restrict__ C2,
    const float* __restrict__ Wf, const float* __restrict__ bf,
    const float* __restrict__ Ws, const float* __restrict__ bs,
    int sidx)
{
    extern __shared__ float smem[];
    float* Xs  = smem;                          // [128][132] (tf32 bits)
    float* Wt  = Xs + 128 * XS_STRIDE;          // [64][132]  (tf32 bits)
    float* wA  = Wt + 64 * XS_STRIDE;           // [64] center coeff 0 (signed)
    float* wB  = wA + 64;                       // [64] center coeff 1 (signed)
    float* bb  = wB + 64;                       // [64] bias term
    float* cs0 = bb + 64;                       // [128] centers
    float* cs1 = cs0 + 128;

    unsigned* Xu = (unsigned*)Xs;
    unsigned* Wu = (unsigned*)Wt;

    const int tid = threadIdx.x;
    const int bm  = blockIdx.x * 128;
    const int bn  = blockIdx.y * 64;

    // zero BN stats for this layer (edge kernel starts only after this retires)
    if (blockIdx.x == 0 && blockIdx.y == 0) {
        if (tid < FDIM) { g_sum[sidx][tid] = 0.0; g_sq[sidx][tid] = 0.0; }
        if (tid == 128) g_cnt[sidx] = 0;
    }

    // ---- load X tile, convert to tf32 ----
    #pragma unroll
    for (int idx = tid; idx < 128 * 32; idx += 256) {
        int m = idx >> 5, kq = idx & 31;
        float4 v = ((const float4*)X)[(bm + m) * 32 + kq];
        unsigned* dst = Xu + m * XS_STRIDE + kq * 4;
        uint4 o;
        o.x = f2tf32(v.x); o.y = f2tf32(v.y); o.z = f2tf32(v.z); o.w = f2tf32(v.w);
        *(uint4*)dst = o;
    }
    // ---- load W tile (rows of Wcat), convert to tf32 ----
    #pragma unroll
    for (int idx = tid; idx < 64 * 64; idx += 256) {
        int cl = idx >> 6, kh = idx & 63;
        int n = bn + cl;
        int g = n >> 7, f = n & 127;
        const float* wb = ((g < 2) ? Wf : Ws) + f * ZW + ((g & 1) ? 128 : 0);
        float2 v = ((const float2*)wb)[kh];
        unsigned* dst = Wu + cl * XS_STRIDE + kh * 2;
        uint2 o; o.x = f2tf32(v.x); o.y = f2tf32(v.y);
        *(uint2*)dst = o;
    }
    // ---- small epilogue tables ----
    if (tid < 64) {
        int n = bn + tid;
        int g = n >> 7, f = n & 127;
        const float* wsel = (g < 2) ? Wf : Ws;
        float sgn = (g & 1) ? -1.f : 1.f;     // g odd: Q-side -> minus center term
        wA[tid] = sgn * wsel[f * ZW + 256];
        wB[tid] = sgn * wsel[f * ZW + 257];
        bb[tid] = (g == 0) ? bf[f] : ((g == 2) ? bs[f] : 0.f);
    }
    if (tid < 128) {
        cs0[tid] = C2[(bm + tid) * 2 + 0];
        cs1[tid] = C2[(bm + tid) * 2 + 1];
    }
    __syncthreads();

    const int wid   = tid >> 5;
    const int lane  = tid & 31;
    const int group = lane >> 2;
    const int tg    = lane & 3;
    const int wm    = (wid & 3) * 32;
    const int wn    = (wid >> 2) * 32;

    // ---- per-lane ldmatrix base addresses (k-step 0) ----
    // A (x4): quadrant q = lane>>3, row-in-q = lane&7
    //   q0:(row+0,k+0) q1:(row+8,k+0) q2:(row+0,k+4) q3:(row+8,k+4)
    unsigned aAddr[2];
    {
        int q = lane >> 3, rq = lane & 7;
        int rowoff = (q & 1) * 8 + rq;
        int koff   = (q >> 1) * 4;
        #pragma unroll
        for (int mt = 0; mt < 2; mt++) {
            int r = wm + mt * 16 + rowoff;
            aAddr[mt] = smem_u32(&Xu[r * XS_STRIDE + koff]);
        }
    }
    // B (x2): lanes 0-7 -> rows of matrix0 (k+0), lanes 8-15 -> matrix1 (k+4)
    unsigned bAddr[4];
    {
        int l16 = lane & 15;
        int rowoff = l16 & 7;
        int koff   = (l16 >> 3) * 4;
        #pragma unroll
        for (int nt = 0; nt < 4; nt++) {
            int nn = wn + nt * 8 + rowoff;
            bAddr[nt] = smem_u32(&Wu[nn * XS_STRIDE + koff]);
        }
    }

    float acc[2][4][4];
    #pragma unroll
    for (int mt = 0; mt < 2; mt++)
        #pragma unroll
        for (int nt = 0; nt < 4; nt++)
            #pragma unroll
            for (int c = 0; c < 4; c++) acc[mt][nt][c] = 0.f;

    // ---- k-loop with 2-deep register pipeline ----
    unsigned af[2][2][4], bfr[2][4][2];

    #pragma unroll
    for (int mt = 0; mt < 2; mt++) ldsm_x4(af[0][mt], aAddr[mt]);
    #pragma unroll
    for (int nt = 0; nt < 4; nt++) ldsm_x2(bfr[0][nt], bAddr[nt]);

    #pragma unroll
    for (int ks = 0; ks < 16; ks++) {
        const int cur = ks & 1, nxt = cur ^ 1;
        if (ks < 15) {
            const unsigned koff = (unsigned)(ks + 1) * 32u;   // 8 floats = 32B
            #pragma unroll
            for (int mt = 0; mt < 2; mt++) ldsm_x4(af[nxt][mt], aAddr[mt] + koff);
            #pragma unroll
            for (int nt = 0; nt < 4; nt++) ldsm_x2(bfr[nxt][nt], bAddr[nt] + koff);
        }
        #pragma unroll
        for (int mt = 0; mt < 2; mt++)
            #pragma unroll
            for (int nt = 0; nt < 4; nt++)
                mma_tf32(acc[mt][nt], af[cur][mt], bfr[cur][nt]);
    }

    // ---- epilogue: center term + bias + exp, scatter to g_E ----
    #pragma unroll
    for (int mt = 0; mt < 2; mt++) {
        int r0 = wm + mt * 16 + group;     // local m for c0,c1
        int r1 = r0 + 8;                   // local m for c2,c3
        float a0 = cs0[r0], a1 = cs1[r0];
        float b0 = cs0[r1], b1 = cs1[r1];
        #pragma unroll
        for (int nt = 0; nt < 4; nt++) {
            int cl = wn + nt * 8 + 2 * tg;
            #pragma unroll
            for (int cc = 0; cc < 4; cc++) {
                int cll = cl + (cc & 1);
                int n = bn + cll;
                int g = n >> 7, f = n & 127;
                float mc0 = (cc < 2) ? a0 : b0;
                float mc1 = (cc < 2) ? a1 : b1;
                int rl = (cc < 2) ? r0 : r1;
                float t = acc[mt][nt][cc] + mc0 * wA[cll] + mc1 * wB[cll] + bb[cll];
                float v = __expf((g < 2) ? -t : t);
                g_E[g][(bm + rl) * FDIM + f] = v;
            }
        }
    }
}

// ---------------- edge aggregation ------------------------------------------
// agg[i,f] = sum_{j != i, same sample} sigmoid(Pf_i+Qf_j) * softplus(Ps_i+Qs_j)
//          = sum_j rcp(1 + A_i*U_j) * ln2 * log2(1 + B_i*V_j)  - self term.
// 4-way reciprocal batching: one RCP per 4 j's via product of denominators.
// Last arriving block finalizes BN scale/shift (FP64 once, 128 threads).
__global__ __launch_bounds__(256) void k_edge(int sidx,
    const float* __restrict__ gamma, const float* __restrict__ beta)
{
    __shared__ float su[4][64];
    __shared__ float sv[4][64];
    __shared__ float wsum[8], wsq[8];
    __shared__ int   lastflag;

    const int tid  = threadIdx.x;
    const int i    = tid & 63;          // agent within sample
    const int fl   = tid >> 6;          // 0..3 local feature
    const int f    = blockIdx.y * 4 + fl;
    const int node = blockIdx.x * NAG + i;
    const int base = node * FDIM + f;

    const float a  = g_E[0][base];
    const float u  = g_E[1][base];
    const float b  = g_E[2][base];
    const float vv = g_E[3][base];
    su[fl][i] = u;
    sv[fl][i] = vv;
    __syncthreads();

    const float4* pu = (const float4*)su[fl];
    const float4* pv = (const float4*)sv[fl];

    float acc = 0.f;
    #pragma unroll
    for (int jq = 0; jq < 16; jq++) {
        float4 U4 = pu[jq];
        float4 V4 = pv[jq];
        float t10 = fmaf(a, U4.x, 1.f);
        float t11 = fmaf(a, U4.y, 1.f);
        float t12 = fmaf(a, U4.z, 1.f);
        float t13 = fmaf(a, U4.w, 1.f);
        float p01 = t10 * t11;
        float p23 = t12 * t13;
        float D   = p01 * p23;
        float r;
        asm("rcp.approx.f32 %0, %1;" : "=f"(r) : "f"(D));
        float l0 = __log2f(fmaf(b, V4.x, 1.f));
        float l1 = __log2f(fmaf(b, V4.y, 1.f));
        float l2 = __log2f(fmaf(b, V4.z, 1.f));
        float l3 = __log2f(fmaf(b, V4.w, 1.f));
        float n0 = t11 * p23;
        float n1 = t10 * p23;
        float n2 = p01 * t13;
        float n3 = p01 * t12;
        float s = fmaf(n0, l0, n1 * l1) + fmaf(n2, l2, n3 * l3);
        acc = fmaf(s, r, acc);
    }
    // subtract self term (j == i)
    {
        float t1 = fmaf(a, u, 1.f);
        float t2 = fmaf(b, vv, 1.f);
        float r;
        asm("rcp.approx.f32 %0, %1;" : "=f"(r) : "f"(t1));
        acc -= r * __log2f(t2);
    }
    const float aggv = acc * LN2F;
    g_agg[base] = aggv;

    // BN stats partial sums (per feature over this block's 64 agents)
    float s = aggv, q = aggv * aggv;
    #pragma unroll
    for (int o = 16; o > 0; o >>= 1) {
        s += __shfl_down_sync(0xFFFFFFFFu, s, o);
        q += __shfl_down_sync(0xFFFFFFFFu, q, o);
    }
    if ((tid & 31) == 0) { wsum[tid >> 5] = s; wsq[tid >> 5] = q; }
    __syncthreads();
    if (tid < 4) {
        double S = (double)wsum[2 * tid] + (double)wsum[2 * tid + 1];
        double Q = (double)wsq[2 * tid]  + (double)wsq[2 * tid + 1];
        int ff = blockIdx.y * 4 + tid;
        atomicAdd(&g_sum[sidx][ff], S);
        atomicAdd(&g_sq[sidx][ff], Q);
        __threadfence();
    }
    __syncthreads();

    // last-arriving block computes BN scale/shift once
    if (tid == 0) {
        int prev = atomicAdd(&g_cnt[sidx], 1);
        lastflag = (prev == NSAMP * (FDIM / 4) - 1);
    }
    __syncthreads();
    if (lastflag) {
        if (tid < FDIM) {
            double S = __ldcg(&g_sum[sidx][tid]);
            double Q = __ldcg(&g_sq[sidx][tid]);
            double mean = S * (1.0 / NNODES);
            double var  = Q * (1.0 / NNODES) - mean * mean;
            float inv = (float)(1.0 / sqrt(var + 1e-5));
            float g = gamma[tid];
            g_sc[sidx][tid] = inv * g;
            g_sh[sidx][tid] = beta[tid] - (float)mean * inv * g;
        }
    }
}

// ---------------- BatchNorm + residual + ReLU (pure fp32 stream) ------------
__global__ __launch_bounds__(256) void k_bn(
    const float* __restrict__ xin,
    float* __restrict__ out, int sidx)
{
    const int t = threadIdx.x;
    const float* sc = g_sc[sidx];
    const float* sh = g_sh[sidx];

    #pragma unroll
    for (int rep = 0; rep < 2; rep++) {
        int q4 = blockIdx.x * 512 + rep * 256 + t;   // float4 index
        int base = q4 * 4;
        int f = base & 127;
        float4 ag = *(const float4*)(g_agg + base);
        float4 xi = *(const float4*)(xin + base);
        float4 scv = *(const float4*)(sc + f);
        float4 shv = *(const float4*)(sh + f);
        float4 o;
        o.x = fmaxf(fmaf(ag.x, scv.x, shv.x) + xi.x, 0.f);
        o.y = fmaxf(fmaf(ag.y, scv.y, shv.y) + xi.y, 0.f);
        o.z = fmaxf(fmaf(ag.z, scv.z, shv.z) + xi.z, 0.f);
        o.w = fmaxf(fmaf(ag.w, scv.w, shv.w) + xi.w, 0.f);
        *(float4*)(out + base) = o;
    }
}

// ---------------- launcher ---------------------------------------------------
extern "C" void kernel_launch(void* const* d_in, const int* in_sizes, int n_in,
                              void* d_out, int out_size)
{
    const float* gnn_in  = (const float*)d_in[0];
    const float* centers = (const float*)d_in[1];
    // d_in[2]=src, d_in[3]=dst unused (graph structure is static)
    const float* Wf1 = (const float*)d_in[4];
    const float* bf1 = (const float*)d_in[5];
    const float* Ws1 = (const float*)d_in[6];
    const float* bs1 = (const float*)d_in[7];
    const float* g1  = (const float*)d_in[8];
    const float* be1 = (const float*)d_in[9];
    const float* Wf2 = (const float*)d_in[10];
    const float* bf2 = (const float*)d_in[11];
    const float* Ws2 = (const float*)d_in[12];
    const float* bs2 = (const float*)d_in[13];
    const float* g2  = (const float*)d_in[14];
    const float* be2 = (const float*)d_in[15];
    float* out = (float*)d_out;

    float* x1;
    cudaGetSymbolAddress((void**)&x1, g_x1);

    static int smem_set = 0;
    if (!smem_set) {
        cudaFuncSetAttribute(k_gemm_tf32,
                             cudaFuncAttributeMaxDynamicSharedMemorySize,
                             GEMM_SMEM_BYTES);
        smem_set = 1;
    }

    dim3 gemm_grid(NNODES / 128, 8);      // 32 x 8 blocks
    dim3 edge_grid(NSAMP, FDIM / 4);      // 64 x 32 blocks
    int bn_blocks = (NNODES * FDIM) / (4 * 512);   // 256 blocks

    // ---- layer 1 ----
    k_gemm_tf32<<<gemm_grid, 256, GEMM_SMEM_BYTES>>>(gnn_in, centers, Wf1, bf1, Ws1, bs1, 0);
    k_edge<<<edge_grid, 256>>>(0, g1, be1);
    k_bn<<<bn_blocks, 256>>>(gnn_in, x1, 0);

    // ---- layer 2 ----
    k_gemm_tf32<<<gemm_grid, 256, GEMM_SMEM_BYTES>>>(x1, centers, Wf2, bf2, Ws2, bs2, 1);
    k_edge<<<edge_grid, 256>>>(1, g2, be2);
    k_bn<<<bn_blocks, 256>>>(x1, out, 1);
}

// round 6
// speedup vs baseline: 2.6534x; 1.1416x over previous
#include <cuda_runtime.h>
#include <cuda_bf16.h>
#include <math.h>

// Problem constants
#define NNODES   4096      // 64 samples * 64 agents
#define NAG      64        // agents per sample
#define NSAMP    64
#define FDIM     128
#define ZW       258       // 2*F + 2
#define LN2F     0.69314718055994530942f

// ---------------- scratch (device globals; no allocations allowed) ----------
// Feature-major: g_E[g][f*NNODES + node].
// g: 0=A=exp(-Pf), 1=U=exp(-Qf), 2=B=exp(+Ps), 3=V=exp(+Qs)
__device__ __align__(16) float  g_E[4][FDIM * NNODES];
__device__ __align__(16) float  g_agg[NNODES * FDIM];    // [node][f]
__device__ __align__(16) float  g_x1[NNODES * FDIM];     // [node][f]
__device__ double g_sum[2][FDIM];
__device__ double g_sq[2][FDIM];
__device__ __align__(16) float g_sc[2][FDIM];
__device__ __align__(16) float g_sh[2][FDIM];
__device__ int    g_cnt[2];

// ---------------- tf32 mma helpers ------------------------------------------
__device__ __forceinline__ unsigned f2tf32(float x) {
    unsigned u;
    asm("cvt.rna.tf32.f32 %0, %1;" : "=r"(u) : "f"(x));
    return u;
}
__device__ __forceinline__ void mma_tf32(float c[4], const unsigned a[4], const unsigned b[2]) {
    asm volatile("mma.sync.aligned.m16n8k8.row.col.f32.tf32.tf32.f32 "
        "{%0,%1,%2,%3}, {%4,%5,%6,%7}, {%8,%9}, {%0,%1,%2,%3};"
        : "+f"(c[0]), "+f"(c[1]), "+f"(c[2]), "+f"(c[3])
        : "r"(a[0]), "r"(a[1]), "r"(a[2]), "r"(a[3]), "r"(b[0]), "r"(b[1]));
}
__device__ __forceinline__ void ldsm_x4(unsigned r[4], unsigned saddr) {
    asm volatile("ldmatrix.sync.aligned.m8n8.x4.shared.b16 {%0,%1,%2,%3}, [%4];"
        : "=r"(r[0]), "=r"(r[1]), "=r"(r[2]), "=r"(r[3]) : "r"(saddr));
}
__device__ __forceinline__ void ldsm_x2(unsigned r[2], unsigned saddr) {
    asm volatile("ldmatrix.sync.aligned.m8n8.x2.shared.b16 {%0,%1}, [%2];"
        : "=r"(r[0]), "=r"(r[1]) : "r"(saddr));
}
__device__ __forceinline__ unsigned smem_u32(const void* p) {
    unsigned a;
    asm("{ .reg .u64 t; cvta.to.shared.u64 t, %1; cvt.u32.u64 %0, t; }"
        : "=r"(a) : "l"(p));
    return a;
}

// ---------------- node GEMM (tf32 tensor core) + exp epilogue ---------------
// C[4096,512] = Xeff[4096,128] @ Wcat[512,128]^T, column n = g*128+f.
// fuse=1 (layer 2): Xeff = relu(BN1(agg) + x0), computed in the prologue
// from g_agg/g_sc[0]/g_sh[0]; blocks with blockIdx.y==0 also write Xeff
// to Xout (g_x1) for the layer-2 residual.
// Epilogue writes exp() results to feature-major g_E.
#define XS_STRIDE 132
#define GEMM_SMEM_FLOATS (128*XS_STRIDE + 64*XS_STRIDE + 64*3 + 128*2)
#define GEMM_SMEM_BYTES  (GEMM_SMEM_FLOATS * 4)

__global__ __launch_bounds__(256, 2) void k_gemm_tf32(
    const float* __restrict__ X,       // x0 (gnn_in) for both layers
    const float* __restrict__ AGG,     // layer-1 agg (fuse only)
    float* __restrict__ Xout,          // x1 destination (fuse only)
    const float* __restrict__ C2,
    const float* __restrict__ Wf, const float* __restrict__ bf,
    const float* __restrict__ Ws, const float* __restrict__ bs,
    int sidx, int fuse)
{
    extern __shared__ float smem[];
    float* Xs  = smem;                          // [128][132] (tf32 bits)
    float* Wt  = Xs + 128 * XS_STRIDE;          // [64][132]  (tf32 bits)
    float* wA  = Wt + 64 * XS_STRIDE;           // [64] center coeff 0 (signed)
    float* wB  = wA + 64;                       // [64] center coeff 1 (signed)
    float* bb  = wB + 64;                       // [64] bias term
    float* cs0 = bb + 64;                       // [128] centers
    float* cs1 = cs0 + 128;

    unsigned* Xu = (unsigned*)Xs;
    unsigned* Wu = (unsigned*)Wt;

    const int tid = threadIdx.x;
    const int bm  = blockIdx.x * 128;
    const int bn  = blockIdx.y * 64;

    // zero BN stats for this layer (edge kernel starts only after this retires)
    if (blockIdx.x == 0 && blockIdx.y == 0) {
        if (tid < FDIM) { g_sum[sidx][tid] = 0.0; g_sq[sidx][tid] = 0.0; }
        if (tid == 128) g_cnt[sidx] = 0;
    }

    // ---- load/compute X tile, convert to tf32 ----
    #pragma unroll
    for (int idx = tid; idx < 128 * 32; idx += 256) {
        int m = idx >> 5, kq = idx & 31;
        float4 v = ((const float4*)X)[(bm + m) * 32 + kq];
        if (fuse) {
            float4 ag  = ((const float4*)AGG)[(bm + m) * 32 + kq];
            float4 scv = *(const float4*)(g_sc[0] + kq * 4);
            float4 shv = *(const float4*)(g_sh[0] + kq * 4);
            v.x = fmaxf(fmaf(ag.x, scv.x, shv.x) + v.x, 0.f);
            v.y = fmaxf(fmaf(ag.y, scv.y, shv.y) + v.y, 0.f);
            v.z = fmaxf(fmaf(ag.z, scv.z, shv.z) + v.z, 0.f);
            v.w = fmaxf(fmaf(ag.w, scv.w, shv.w) + v.w, 0.f);
            if (blockIdx.y == 0) ((float4*)Xout)[(bm + m) * 32 + kq] = v;
        }
        unsigned* dst = Xu + m * XS_STRIDE + kq * 4;
        uint4 o;
        o.x = f2tf32(v.x); o.y = f2tf32(v.y); o.z = f2tf32(v.z); o.w = f2tf32(v.w);
        *(uint4*)dst = o;
    }
    // ---- load W tile (rows of Wcat), convert to tf32 ----
    #pragma unroll
    for (int idx = tid; idx < 64 * 64; idx += 256) {
        int cl = idx >> 6, kh = idx & 63;
        int n = bn + cl;
        int g = n >> 7, f = n & 127;
        const float* wb = ((g < 2) ? Wf : Ws) + f * ZW + ((g & 1) ? 128 : 0);
        float2 v = ((const float2*)wb)[kh];
        unsigned* dst = Wu + cl * XS_STRIDE + kh * 2;
        uint2 o; o.x = f2tf32(v.x); o.y = f2tf32(v.y);
        *(uint2*)dst = o;
    }
    // ---- small epilogue tables ----
    if (tid < 64) {
        int n = bn + tid;
        int g = n >> 7, f = n & 127;
        const float* wsel = (g < 2) ? Wf : Ws;
        float sgn = (g & 1) ? -1.f : 1.f;     // g odd: Q-side -> minus center term
        wA[tid] = sgn * wsel[f * ZW + 256];
        wB[tid] = sgn * wsel[f * ZW + 257];
        bb[tid] = (g == 0) ? bf[f] : ((g == 2) ? bs[f] : 0.f);
    }
    if (tid < 128) {
        cs0[tid] = C2[(bm + tid) * 2 + 0];
        cs1[tid] = C2[(bm + tid) * 2 + 1];
    }
    __syncthreads();

    const int wid   = tid >> 5;
    const int lane  = tid & 31;
    const int group = lane >> 2;
    const int tg    = lane & 3;
    const int wm    = (wid & 3) * 32;
    const int wn    = (wid >> 2) * 32;

    // ---- per-lane ldmatrix base addresses (k-step 0) ----
    unsigned aAddr[2];
    {
        int q = lane >> 3, rq = lane & 7;
        int rowoff = (q & 1) * 8 + rq;
        int koff   = (q >> 1) * 4;
        #pragma unroll
        for (int mt = 0; mt < 2; mt++) {
            int r = wm + mt * 16 + rowoff;
            aAddr[mt] = smem_u32(&Xu[r * XS_STRIDE + koff]);
        }
    }
    unsigned bAddr[4];
    {
        int l16 = lane & 15;
        int rowoff = l16 & 7;
        int koff   = (l16 >> 3) * 4;
        #pragma unroll
        for (int nt = 0; nt < 4; nt++) {
            int nn = wn + nt * 8 + rowoff;
            bAddr[nt] = smem_u32(&Wu[nn * XS_STRIDE + koff]);
        }
    }

    float acc[2][4][4];
    #pragma unroll
    for (int mt = 0; mt < 2; mt++)
        #pragma unroll
        for (int nt = 0; nt < 4; nt++)
            #pragma unroll
            for (int c = 0; c < 4; c++) acc[mt][nt][c] = 0.f;

    // ---- k-loop with 2-deep register pipeline ----
    unsigned af[2][2][4], bfr[2][4][2];
    #pragma unroll
    for (int mt = 0; mt < 2; mt++) ldsm_x4(af[0][mt], aAddr[mt]);
    #pragma unroll
    for (int nt = 0; nt < 4; nt++) ldsm_x2(bfr[0][nt], bAddr[nt]);

    #pragma unroll
    for (int ks = 0; ks < 16; ks++) {
        const int cur = ks & 1, nxt = cur ^ 1;
        if (ks < 15) {
            const unsigned koff = (unsigned)(ks + 1) * 32u;
            #pragma unroll
            for (int mt = 0; mt < 2; mt++) ldsm_x4(af[nxt][mt], aAddr[mt] + koff);
            #pragma unroll
            for (int nt = 0; nt < 4; nt++) ldsm_x2(bfr[nxt][nt], bAddr[nt] + koff);
        }
        #pragma unroll
        for (int mt = 0; mt < 2; mt++)
            #pragma unroll
            for (int nt = 0; nt < 4; nt++)
                mma_tf32(acc[mt][nt], af[cur][mt], bfr[cur][nt]);
    }

    // ---- epilogue: center term + bias + exp, feature-major scatter ----
    // lanes vary over contiguous nodes -> full 32B sectors.
    #pragma unroll
    for (int mt = 0; mt < 2; mt++) {
        int r0 = wm + mt * 16 + group;
        int r1 = r0 + 8;
        float a0 = cs0[r0], a1 = cs1[r0];
        float b0 = cs0[r1], b1 = cs1[r1];
        #pragma unroll
        for (int nt = 0; nt < 4; nt++) {
            int cl = wn + nt * 8 + 2 * tg;
            #pragma unroll
            for (int cc = 0; cc < 4; cc++) {
                int cll = cl + (cc & 1);
                int n = bn + cll;
                int g = n >> 7, f = n & 127;
                float mc0 = (cc < 2) ? a0 : b0;
                float mc1 = (cc < 2) ? a1 : b1;
                int rl = (cc < 2) ? r0 : r1;
                float t = acc[mt][nt][cc] + mc0 * wA[cll] + mc1 * wB[cll] + bb[cll];
                float v = __expf((g < 2) ? -t : t);
                g_E[g][f * NNODES + bm + rl] = v;
            }
        }
    }
}

// ---------------- edge aggregation ------------------------------------------
// agg[i,f] = sum_{j != i, same sample} sigmoid(Pf_i+Qf_j)*softplus(Ps_i+Qs_j)
// 4-way reciprocal batching; feature-major g_E loads (fully coalesced).
// Last arriving block finalizes BN scale/shift.
__global__ __launch_bounds__(256) void k_edge(int sidx,
    const float* __restrict__ gamma, const float* __restrict__ beta)
{
    __shared__ float su[4][64];
    __shared__ float sv[4][64];
    __shared__ float wsum[8], wsq[8];
    __shared__ int   lastflag;

    const int tid  = threadIdx.x;
    const int i    = tid & 63;          // agent within sample
    const int fl   = tid >> 6;          // 0..3 local feature
    const int f    = blockIdx.y * 4 + fl;
    const int node = blockIdx.x * NAG + i;
    const int eidx = f * NNODES + node;

    const float a  = g_E[0][eidx];
    const float u  = g_E[1][eidx];
    const float b  = g_E[2][eidx];
    const float vv = g_E[3][eidx];
    su[fl][i] = u;
    sv[fl][i] = vv;
    __syncthreads();

    const float4* pu = (const float4*)su[fl];
    const float4* pv = (const float4*)sv[fl];

    float acc = 0.f;
    #pragma unroll
    for (int jq = 0; jq < 16; jq++) {
        float4 U4 = pu[jq];
        float4 V4 = pv[jq];
        float t10 = fmaf(a, U4.x, 1.f);
        float t11 = fmaf(a, U4.y, 1.f);
        float t12 = fmaf(a, U4.z, 1.f);
        float t13 = fmaf(a, U4.w, 1.f);
        float p01 = t10 * t11;
        float p23 = t12 * t13;
        float D   = p01 * p23;
        float r;
        asm("rcp.approx.f32 %0, %1;" : "=f"(r) : "f"(D));
        float l0 = __log2f(fmaf(b, V4.x, 1.f));
        float l1 = __log2f(fmaf(b, V4.y, 1.f));
        float l2 = __log2f(fmaf(b, V4.z, 1.f));
        float l3 = __log2f(fmaf(b, V4.w, 1.f));
        float n0 = t11 * p23;
        float n1 = t10 * p23;
        float n2 = p01 * t13;
        float n3 = p01 * t12;
        float s = fmaf(n0, l0, n1 * l1) + fmaf(n2, l2, n3 * l3);
        acc = fmaf(s, r, acc);
    }
    // subtract self term (j == i)
    {
        float t1 = fmaf(a, u, 1.f);
        float t2 = fmaf(b, vv, 1.f);
        float r;
        asm("rcp.approx.f32 %0, %1;" : "=f"(r) : "f"(t1));
        acc -= r * __log2f(t2);
    }
    const float aggv = acc * LN2F;
    g_agg[node * FDIM + f] = aggv;

    // BN stats partial sums (per feature over this block's 64 agents)
    float s = aggv, q = aggv * aggv;
    #pragma unroll
    for (int o = 16; o > 0; o >>= 1) {
        s += __shfl_down_sync(0xFFFFFFFFu, s, o);
        q += __shfl_down_sync(0xFFFFFFFFu, q, o);
    }
    if ((tid & 31) == 0) { wsum[tid >> 5] = s; wsq[tid >> 5] = q; }
    __syncthreads();
    if (tid < 4) {
        double S = (double)wsum[2 * tid] + (double)wsum[2 * tid + 1];
        double Q = (double)wsq[2 * tid]  + (double)wsq[2 * tid + 1];
        int ff = blockIdx.y * 4 + tid;
        atomicAdd(&g_sum[sidx][ff], S);
        atomicAdd(&g_sq[sidx][ff], Q);
        __threadfence();
    }
    __syncthreads();

    if (tid == 0) {
        int prev = atomicAdd(&g_cnt[sidx], 1);
        lastflag = (prev == NSAMP * (FDIM / 4) - 1);
    }
    __syncthreads();
    if (lastflag) {
        if (tid < FDIM) {
            double S = __ldcg(&g_sum[sidx][tid]);
            double Q = __ldcg(&g_sq[sidx][tid]);
            double mean = S * (1.0 / NNODES);
            double var  = Q * (1.0 / NNODES) - mean * mean;
            float inv = (float)(1.0 / sqrt(var + 1e-5));
            float g = gamma[tid];
            g_sc[sidx][tid] = inv * g;
            g_sh[sidx][tid] = beta[tid] - (float)mean * inv * g;
        }
    }
}

// ---------------- BatchNorm + residual + ReLU (final output) ----------------
__global__ __launch_bounds__(256) void k_bn(
    const float* __restrict__ xin,
    float* __restrict__ out, int sidx)
{
    const int t = threadIdx.x;
    const float* sc = g_sc[sidx];
    const float* sh = g_sh[sidx];

    #pragma unroll
    for (int rep = 0; rep < 2; rep++) {
        int q4 = blockIdx.x * 512 + rep * 256 + t;
        int base = q4 * 4;
        int f = base & 127;
        float4 ag = *(const float4*)(g_agg + base);
        float4 xi = *(const float4*)(xin + base);
        float4 scv = *(const float4*)(sc + f);
        float4 shv = *(const float4*)(sh + f);
        float4 o;
        o.x = fmaxf(fmaf(ag.x, scv.x, shv.x) + xi.x, 0.f);
        o.y = fmaxf(fmaf(ag.y, scv.y, shv.y) + xi.y, 0.f);
        o.z = fmaxf(fmaf(ag.z, scv.z, shv.z) + xi.z, 0.f);
        o.w = fmaxf(fmaf(ag.w, scv.w, shv.w) + xi.w, 0.f);
        *(float4*)(out + base) = o;
    }
}

// ---------------- launcher ---------------------------------------------------
extern "C" void kernel_launch(void* const* d_in, const int* in_sizes, int n_in,
                              void* d_out, int out_size)
{
    const float* gnn_in  = (const float*)d_in[0];
    const float* centers = (const float*)d_in[1];
    // d_in[2]=src, d_in[3]=dst unused (graph structure is static)
    const float* Wf1 = (const float*)d_in[4];
    const float* bf1 = (const float*)d_in[5];
    const float* Ws1 = (const float*)d_in[6];
    const float* bs1 = (const float*)d_in[7];
    const float* g1  = (const float*)d_in[8];
    const float* be1 = (const float*)d_in[9];
    const float* Wf2 = (const float*)d_in[10];
    const float* bf2 = (const float*)d_in[11];
    const float* Ws2 = (const float*)d_in[12];
    const float* bs2 = (const float*)d_in[13];
    const float* g2  = (const float*)d_in[14];
    const float* be2 = (const float*)d_in[15];
    float* out = (float*)d_out;

    float* x1;   cudaGetSymbolAddress((void**)&x1, g_x1);
    float* aggp; cudaGetSymbolAddress((void**)&aggp, g_agg);

    static int smem_set = 0;
    if (!smem_set) {
        cudaFuncSetAttribute(k_gemm_tf32,
                             cudaFuncAttributeMaxDynamicSharedMemorySize,
                             GEMM_SMEM_BYTES);
        smem_set = 1;
    }

    dim3 gemm_grid(NNODES / 128, 8);      // 32 x 8 blocks
    dim3 edge_grid(NSAMP, FDIM / 4);      // 64 x 32 blocks
    int bn_blocks = (NNODES * FDIM) / (4 * 512);   // 256 blocks

    // ---- layer 1 ----
    k_gemm_tf32<<<gemm_grid, 256, GEMM_SMEM_BYTES>>>(
        gnn_in, gnn_in, x1, centers, Wf1, bf1, Ws1, bs1, 0, 0);
    k_edge<<<edge_grid, 256>>>(0, g1, be1);

    // ---- layer 2 (BN1 + residual + ReLU fused into the GEMM prologue) ----
    k_gemm_tf32<<<gemm_grid, 256, GEMM_SMEM_BYTES>>>(
        gnn_in, aggp, x1, centers, Wf2, bf2, Ws2, bs2, 1, 1);
    k_edge<<<edge_grid, 256>>>(1, g2, be2);
    k_bn<<<bn_blocks, 256>>>(x1, out, 1);
}

// round 7
// speedup vs baseline: 2.8531x; 1.0752x over previous
#include <cuda_runtime.h>
#include <cuda_bf16.h>
#include <math.h>

// Problem constants
#define NNODES   4096      // 64 samples * 64 agents
#define NAG      64        // agents per sample
#define NSAMP    64
#define FDIM     128
#define ZW       258       // 2*F + 2
#define LN2F     0.69314718055994530942f

// ---------------- scratch (device globals; no allocations allowed) ----------
// Feature-major: g_E[g][f*NNODES + node].
// g: 0=A=exp(-Pf), 1=U=exp(-Qf), 2=B=exp(+Ps), 3=V=exp(+Qs)
__device__ __align__(16) float  g_E[4][FDIM * NNODES];
__device__ __align__(16) float  g_agg[NNODES * FDIM];    // [node][f]
__device__ __align__(16) float  g_x1[NNODES * FDIM];     // [node][f]
__device__ double g_sum[2][FDIM];
__device__ double g_sq[2][FDIM];
__device__ __align__(16) float g_sc[2][FDIM];
__device__ __align__(16) float g_sh[2][FDIM];
__device__ int    g_cnt[2];

// ---------------- tf32 mma helpers ------------------------------------------
__device__ __forceinline__ unsigned f2tf32(float x) {
    unsigned u;
    asm("cvt.rna.tf32.f32 %0, %1;" : "=r"(u) : "f"(x));
    return u;
}
__device__ __forceinline__ void mma_tf32(float c[4], const unsigned a[4], const unsigned b[2]) {
    asm volatile("mma.sync.aligned.m16n8k8.row.col.f32.tf32.tf32.f32 "
        "{%0,%1,%2,%3}, {%4,%5,%6,%7}, {%8,%9}, {%0,%1,%2,%3};"
        : "+f"(c[0]), "+f"(c[1]), "+f"(c[2]), "+f"(c[3])
        : "r"(a[0]), "r"(a[1]), "r"(a[2]), "r"(a[3]), "r"(b[0]), "r"(b[1]));
}
__device__ __forceinline__ void ldsm_x4(unsigned r[4], unsigned saddr) {
    asm volatile("ldmatrix.sync.aligned.m8n8.x4.shared.b16 {%0,%1,%2,%3}, [%4];"
        : "=r"(r[0]), "=r"(r[1]), "=r"(r[2]), "=r"(r[3]) : "r"(saddr));
}
__device__ __forceinline__ void ldsm_x2(unsigned r[2], unsigned saddr) {
    asm volatile("ldmatrix.sync.aligned.m8n8.x2.shared.b16 {%0,%1}, [%2];"
        : "=r"(r[0]), "=r"(r[1]) : "r"(saddr));
}
__device__ __forceinline__ unsigned smem_u32(const void* p) {
    unsigned a;
    asm("{ .reg .u64 t; cvta.to.shared.u64 t, %1; cvt.u32.u64 %0, t; }"
        : "=r"(a) : "l"(p));
    return a;
}

// ---------------- f32x2 packed helpers (Blackwell) ---------------------------
__device__ __forceinline__ unsigned long long pack2(float lo, float hi) {
    unsigned long long r;
    asm("mov.b64 %0, {%1, %2};" : "=l"(r) : "f"(lo), "f"(hi));
    return r;
}
__device__ __forceinline__ void unpack2(unsigned long long p, float& lo, float& hi) {
    asm("mov.b64 {%0, %1}, %2;" : "=f"(lo), "=f"(hi) : "l"(p));
}
__device__ __forceinline__ unsigned long long fma2(unsigned long long a,
                                                   unsigned long long b,
                                                   unsigned long long c) {
    unsigned long long r;
    asm("fma.rn.f32x2 %0, %1, %2, %3;" : "=l"(r) : "l"(a), "l"(b), "l"(c));
    return r;
}
__device__ __forceinline__ unsigned long long mul2(unsigned long long a,
                                                   unsigned long long b) {
    unsigned long long r;
    asm("mul.rn.f32x2 %0, %1, %2;" : "=l"(r) : "l"(a), "l"(b));
    return r;
}

// ---------------- node GEMM (tf32 tensor core) + exp epilogue ---------------
// C[4096,512] = Xeff[4096,128] @ Wcat[512,128]^T, column n = g*128+f.
// fuse=1 (layer 2): Xeff = relu(BN1(agg) + x0) computed in the prologue;
// blockIdx.y==0 blocks also write Xeff to Xout.
#define XS_STRIDE 132
#define GEMM_SMEM_FLOATS (128*XS_STRIDE + 64*XS_STRIDE + 64*3 + 128*2)
#define GEMM_SMEM_BYTES  (GEMM_SMEM_FLOATS * 4)

__global__ __launch_bounds__(256, 2) void k_gemm_tf32(
    const float* __restrict__ X,       // x0 (gnn_in) for both layers
    const float* __restrict__ AGG,     // layer-1 agg (fuse only)
    float* __restrict__ Xout,          // x1 destination (fuse only)
    const float* __restrict__ C2,
    const float* __restrict__ Wf, const float* __restrict__ bf,
    const float* __restrict__ Ws, const float* __restrict__ bs,
    int sidx, int fuse)
{
    extern __shared__ float smem[];
    float* Xs  = smem;                          // [128][132] (tf32 bits)
    float* Wt  = Xs + 128 * XS_STRIDE;          // [64][132]  (tf32 bits)
    float* wA  = Wt + 64 * XS_STRIDE;           // [64]
    float* wB  = wA + 64;                       // [64]
    float* bb  = wB + 64;                       // [64]
    float* cs0 = bb + 64;                       // [128]
    float* cs1 = cs0 + 128;

    unsigned* Xu = (unsigned*)Xs;
    unsigned* Wu = (unsigned*)Wt;

    const int tid = threadIdx.x;
    const int bm  = blockIdx.x * 128;
    const int bn  = blockIdx.y * 64;

    if (blockIdx.x == 0 && blockIdx.y == 0) {
        if (tid < FDIM) { g_sum[sidx][tid] = 0.0; g_sq[sidx][tid] = 0.0; }
        if (tid == 128) g_cnt[sidx] = 0;
    }

    // ---- load/compute X tile, convert to tf32 ----
    #pragma unroll
    for (int idx = tid; idx < 128 * 32; idx += 256) {
        int m = idx >> 5, kq = idx & 31;
        float4 v = ((const float4*)X)[(bm + m) * 32 + kq];
        if (fuse) {
            float4 ag  = ((const float4*)AGG)[(bm + m) * 32 + kq];
            float4 scv = *(const float4*)(g_sc[0] + kq * 4);
            float4 shv = *(const float4*)(g_sh[0] + kq * 4);
            v.x = fmaxf(fmaf(ag.x, scv.x, shv.x) + v.x, 0.f);
            v.y = fmaxf(fmaf(ag.y, scv.y, shv.y) + v.y, 0.f);
            v.z = fmaxf(fmaf(ag.z, scv.z, shv.z) + v.z, 0.f);
            v.w = fmaxf(fmaf(ag.w, scv.w, shv.w) + v.w, 0.f);
            if (blockIdx.y == 0) ((float4*)Xout)[(bm + m) * 32 + kq] = v;
        }
        unsigned* dst = Xu + m * XS_STRIDE + kq * 4;
        uint4 o;
        o.x = f2tf32(v.x); o.y = f2tf32(v.y); o.z = f2tf32(v.z); o.w = f2tf32(v.w);
        *(uint4*)dst = o;
    }
    // ---- load W tile ----
    #pragma unroll
    for (int idx = tid; idx < 64 * 64; idx += 256) {
        int cl = idx >> 6, kh = idx & 63;
        int n = bn + cl;
        int g = n >> 7, f = n & 127;
        const float* wb = ((g < 2) ? Wf : Ws) + f * ZW + ((g & 1) ? 128 : 0);
        float2 v = ((const float2*)wb)[kh];
        unsigned* dst = Wu + cl * XS_STRIDE + kh * 2;
        uint2 o; o.x = f2tf32(v.x); o.y = f2tf32(v.y);
        *(uint2*)dst = o;
    }
    // ---- small epilogue tables ----
    if (tid < 64) {
        int n = bn + tid;
        int g = n >> 7, f = n & 127;
        const float* wsel = (g < 2) ? Wf : Ws;
        float sgn = (g & 1) ? -1.f : 1.f;
        wA[tid] = sgn * wsel[f * ZW + 256];
        wB[tid] = sgn * wsel[f * ZW + 257];
        bb[tid] = (g == 0) ? bf[f] : ((g == 2) ? bs[f] : 0.f);
    }
    if (tid < 128) {
        cs0[tid] = C2[(bm + tid) * 2 + 0];
        cs1[tid] = C2[(bm + tid) * 2 + 1];
    }
    __syncthreads();

    const int wid   = tid >> 5;
    const int lane  = tid & 31;
    const int group = lane >> 2;
    const int tg    = lane & 3;
    const int wm    = (wid & 3) * 32;
    const int wn    = (wid >> 2) * 32;

    unsigned aAddr[2];
    {
        int q = lane >> 3, rq = lane & 7;
        int rowoff = (q & 1) * 8 + rq;
        int koff   = (q >> 1) * 4;
        #pragma unroll
        for (int mt = 0; mt < 2; mt++) {
            int r = wm + mt * 16 + rowoff;
            aAddr[mt] = smem_u32(&Xu[r * XS_STRIDE + koff]);
        }
    }
    unsigned bAddr[4];
    {
        int l16 = lane & 15;
        int rowoff = l16 & 7;
        int koff   = (l16 >> 3) * 4;
        #pragma unroll
        for (int nt = 0; nt < 4; nt++) {
            int nn = wn + nt * 8 + rowoff;
            bAddr[nt] = smem_u32(&Wu[nn * XS_STRIDE + koff]);
        }
    }

    float acc[2][4][4];
    #pragma unroll
    for (int mt = 0; mt < 2; mt++)
        #pragma unroll
        for (int nt = 0; nt < 4; nt++)
            #pragma unroll
            for (int c = 0; c < 4; c++) acc[mt][nt][c] = 0.f;

    unsigned af[2][2][4], bfr[2][4][2];
    #pragma unroll
    for (int mt = 0; mt < 2; mt++) ldsm_x4(af[0][mt], aAddr[mt]);
    #pragma unroll
    for (int nt = 0; nt < 4; nt++) ldsm_x2(bfr[0][nt], bAddr[nt]);

    #pragma unroll
    for (int ks = 0; ks < 16; ks++) {
        const int cur = ks & 1, nxt = cur ^ 1;
        if (ks < 15) {
            const unsigned koff = (unsigned)(ks + 1) * 32u;
            #pragma unroll
            for (int mt = 0; mt < 2; mt++) ldsm_x4(af[nxt][mt], aAddr[mt] + koff);
            #pragma unroll
            for (int nt = 0; nt < 4; nt++) ldsm_x2(bfr[nxt][nt], bAddr[nt] + koff);
        }
        #pragma unroll
        for (int mt = 0; mt < 2; mt++)
            #pragma unroll
            for (int nt = 0; nt < 4; nt++)
                mma_tf32(acc[mt][nt], af[cur][mt], bfr[cur][nt]);
    }

    // ---- epilogue: center term + bias + exp, feature-major scatter ----
    #pragma unroll
    for (int mt = 0; mt < 2; mt++) {
        int r0 = wm + mt * 16 + group;
        int r1 = r0 + 8;
        float a0 = cs0[r0], a1 = cs1[r0];
        float b0 = cs0[r1], b1 = cs1[r1];
        #pragma unroll
        for (int nt = 0; nt < 4; nt++) {
            int cl = wn + nt * 8 + 2 * tg;
            #pragma unroll
            for (int cc = 0; cc < 4; cc++) {
                int cll = cl + (cc & 1);
                int n = bn + cll;
                int g = n >> 7, f = n & 127;
                float mc0 = (cc < 2) ? a0 : b0;
                float mc1 = (cc < 2) ? a1 : b1;
                int rl = (cc < 2) ? r0 : r1;
                float t = acc[mt][nt][cc] + mc0 * wA[cll] + mc1 * wB[cll] + bb[cll];
                float v = __expf((g < 2) ? -t : t);
                g_E[g][f * NNODES + bm + rl] = v;
            }
        }
    }
}

// ---------------- edge aggregation ------------------------------------------
// agg[i,f] = sum_{j != i} rcp(1 + A_i U_j) * ln2 * log2(1 + B_i V_j)
// 4-way rcp batching with f32x2 packed FMA math:
//   t1a=(t0,t1), t1b=(t2,t3); tt = t1a*t1b = (t0t2, t1t3); D = ttl*tth
//   sum l_k n_k = tth*(l0t2+l2t0) + ttl*(l1t3+l3t1)
//   packed m = (l0,l1)*(t2,t3) + (l2,l3)*(t0,t1) = (m0, m1)
__global__ __launch_bounds__(256) void k_edge(int sidx,
    const float* __restrict__ gamma, const float* __restrict__ beta)
{
    __shared__ __align__(16) float su[4][64];
    __shared__ __align__(16) float sv[4][64];
    __shared__ float wsum[8], wsq[8];
    __shared__ int   lastflag;

    const int tid  = threadIdx.x;
    const int i    = tid & 63;
    const int fl   = tid >> 6;
    const int f    = blockIdx.y * 4 + fl;
    const int node = blockIdx.x * NAG + i;
    const int eidx = f * NNODES + node;

    const float a  = g_E[0][eidx];
    const float u  = g_E[1][eidx];
    const float b  = g_E[2][eidx];
    const float vv = g_E[3][eidx];
    su[fl][i] = u;
    sv[fl][i] = vv;
    __syncthreads();

    const ulonglong2* pu = (const ulonglong2*)su[fl];
    const ulonglong2* pv = (const ulonglong2*)sv[fl];

    const unsigned long long ONE2 = pack2(1.f, 1.f);
    const unsigned long long a2   = pack2(a, a);
    const unsigned long long b2   = pack2(b, b);

    float acc = 0.f;
    #pragma unroll
    for (int jq = 0; jq < 16; jq++) {
        ulonglong2 Uq = pu[jq];     // (u0,u1),(u2,u3)
        ulonglong2 Vq = pv[jq];
        unsigned long long t1a = fma2(a2, Uq.x, ONE2);   // (t0,t1)
        unsigned long long t1b = fma2(a2, Uq.y, ONE2);   // (t2,t3)
        unsigned long long t2a = fma2(b2, Vq.x, ONE2);
        unsigned long long t2b = fma2(b2, Vq.y, ONE2);
        float x0, x1, x2, x3;
        unpack2(t2a, x0, x1);
        unpack2(t2b, x2, x3);
        float l0 = __log2f(x0), l1 = __log2f(x1);
        float l2 = __log2f(x2), l3 = __log2f(x3);
        unsigned long long tt = mul2(t1a, t1b);          // (t0t2, t1t3)
        float ttl, tth;
        unpack2(tt, ttl, tth);
        float D = ttl * tth;
        float r;
        asm("rcp.approx.f32 %0, %1;" : "=f"(r) : "f"(D));
        unsigned long long lp01 = pack2(l0, l1);
        unsigned long long lp23 = pack2(l2, l3);
        unsigned long long m = fma2(lp23, t1a, mul2(lp01, t1b));  // (m0,m1)
        float m0, m1;
        unpack2(m, m0, m1);
        float s = fmaf(ttl, m1, tth * m0);
        acc = fmaf(s, r, acc);
    }
    // subtract self term (j == i)
    {
        float t1 = fmaf(a, u, 1.f);
        float t2 = fmaf(b, vv, 1.f);
        float r;
        asm("rcp.approx.f32 %0, %1;" : "=f"(r) : "f"(t1));
        acc -= r * __log2f(t2);
    }
    const float aggv = acc * LN2F;
    g_agg[node * FDIM + f] = aggv;

    // BN stats partial sums
    float s = aggv, q = aggv * aggv;
    #pragma unroll
    for (int o = 16; o > 0; o >>= 1) {
        s += __shfl_down_sync(0xFFFFFFFFu, s, o);
        q += __shfl_down_sync(0xFFFFFFFFu, q, o);
    }
    if ((tid & 31) == 0) { wsum[tid >> 5] = s; wsq[tid >> 5] = q; }
    __syncthreads();
    if (tid < 4) {
        double S = (double)wsum[2 * tid] + (double)wsum[2 * tid + 1];
        double Q = (double)wsq[2 * tid]  + (double)wsq[2 * tid + 1];
        int ff = blockIdx.y * 4 + tid;
        atomicAdd(&g_sum[sidx][ff], S);
        atomicAdd(&g_sq[sidx][ff], Q);
        __threadfence();
    }
    __syncthreads();

    if (tid == 0) {
        int prev = atomicAdd(&g_cnt[sidx], 1);
        lastflag = (prev == NSAMP * (FDIM / 4) - 1);
    }
    __syncthreads();
    if (lastflag) {
        if (tid < FDIM) {
            double S = __ldcg(&g_sum[sidx][tid]);
            double Q = __ldcg(&g_sq[sidx][tid]);
            double mean = S * (1.0 / NNODES);
            double var  = Q * (1.0 / NNODES) - mean * mean;
            float inv = (float)(1.0 / sqrt(var + 1e-5));
            float g = gamma[tid];
            g_sc[sidx][tid] = inv * g;
            g_sh[sidx][tid] = beta[tid] - (float)mean * inv * g;
        }
    }
}

// ---------------- BatchNorm + residual + ReLU (final output) ----------------
__global__ __launch_bounds__(256) void k_bn(
    const float* __restrict__ xin,
    float* __restrict__ out, int sidx)
{
    const int t = threadIdx.x;
    const float* sc = g_sc[sidx];
    const float* sh = g_sh[sidx];

    #pragma unroll
    for (int rep = 0; rep < 2; rep++) {
        int q4 = blockIdx.x * 512 + rep * 256 + t;
        int base = q4 * 4;
        int f = base & 127;
        float4 ag = *(const float4*)(g_agg + base);
        float4 xi = *(const float4*)(xin + base);
        float4 scv = *(const float4*)(sc + f);
        float4 shv = *(const float4*)(sh + f);
        float4 o;
        o.x = fmaxf(fmaf(ag.x, scv.x, shv.x) + xi.x, 0.f);
        o.y = fmaxf(fmaf(ag.y, scv.y, shv.y) + xi.y, 0.f);
        o.z = fmaxf(fmaf(ag.z, scv.z, shv.z) + xi.z, 0.f);
        o.w = fmaxf(fmaf(ag.w, scv.w, shv.w) + xi.w, 0.f);
        *(float4*)(out + base) = o;
    }
}

// ---------------- launcher ---------------------------------------------------
extern "C" void kernel_launch(void* const* d_in, const int* in_sizes, int n_in,
                              void* d_out, int out_size)
{
    const float* gnn_in  = (const float*)d_in[0];
    const float* centers = (const float*)d_in[1];
    const float* Wf1 = (const float*)d_in[4];
    const float* bf1 = (const float*)d_in[5];
    const float* Ws1 = (const float*)d_in[6];
    const float* bs1 = (const float*)d_in[7];
    const float* g1  = (const float*)d_in[8];
    const float* be1 = (const float*)d_in[9];
    const float* Wf2 = (const float*)d_in[10];
    const float* bf2 = (const float*)d_in[11];
    const float* Ws2 = (const float*)d_in[12];
    const float* bs2 = (const float*)d_in[13];
    const float* g2  = (const float*)d_in[14];
    const float* be2 = (const float*)d_in[15];
    float* out = (float*)d_out;

    float* x1;   cudaGetSymbolAddress((void**)&x1, g_x1);
    float* aggp; cudaGetSymbolAddress((void**)&aggp, g_agg);

    static int smem_set = 0;
    if (!smem_set) {
        cudaFuncSetAttribute(k_gemm_tf32,
                             cudaFuncAttributeMaxDynamicSharedMemorySize,
                             GEMM_SMEM_BYTES);
        smem_set = 1;
    }

    dim3 gemm_grid(NNODES / 128, 8);
    dim3 edge_grid(NSAMP, FDIM / 4);
    int bn_blocks = (NNODES * FDIM) / (4 * 512);

    // ---- layer 1 ----
    k_gemm_tf32<<<gemm_grid, 256, GEMM_SMEM_BYTES>>>(
        gnn_in, gnn_in, x1, centers, Wf1, bf1, Ws1, bs1, 0, 0);
    k_edge<<<edge_grid, 256>>>(0, g1, be1);

    // ---- layer 2 (BN1 + residual + ReLU fused into the GEMM prologue) ----
    k_gemm_tf32<<<gemm_grid, 256, GEMM_SMEM_BYTES>>>(
        gnn_in, aggp, x1, centers, Wf2, bf2, Ws2, bs2, 1, 1);
    k_edge<<<edge_grid, 256>>>(1, g2, be2);
    k_bn<<<bn_blocks, 256>>>(x1, out, 1);
}